// round 11
// baseline (speedup 1.0000x reference)
#include <cuda_runtime.h>
#include <cuda_fp16.h>
#include <cstdint>
#include <cfloat>

// ---------------------------------------------------------------------------
// Problem constants
// ---------------------------------------------------------------------------
#define BATCH 4
#define SEQ   4096
#define DM    512
#define DK    32
#define BS_ROWS (BATCH * SEQ)           // 16384
static const float INV_DK = 0.17677669529663687f;   // 1/sqrt(32)
#define NINF_F (-1e24f)

// ---------------------------------------------------------------------------
// Scratch (static device globals; allocations are forbidden)
// ---------------------------------------------------------------------------
static __device__ int      g_mask_mode;
static __device__ float    g_qk[BS_ROWS * 64];                   // q | k
static __device__ float    g_crow[BS_ROWS];
static __device__ float    g_padf[BS_ROWS];
static __device__ float    g_h[(size_t)BS_ROWS * DM];            // 32 MB
static __device__ float    g_z[(size_t)BS_ROWS * DM];            // 32 MB
static __device__ __half   g_xh[(size_t)BS_ROWS * DM];           // x fp16
static __device__ __half   g_vt[(size_t)BATCH * DM * SEQ];       // V^T fp16
static __device__ __half   g_zhi[(size_t)BS_ROWS * DM];
static __device__ __half   g_zlo[(size_t)BS_ROWS * DM];
static __device__ float    g_wqk[DM * 64];                       // Wq|Wk fp32
static __device__ __half   g_wvt[DM * DM];
static __device__ __half   g_wfhi[DM * DM];

// ---------------------------------------------------------------------------
// PTX helpers (generic compute_103 safe)
// ---------------------------------------------------------------------------
__device__ __forceinline__ uint32_t smem_u32(const void* p) {
    uint32_t a;
    asm("{ .reg .u64 t; cvta.to.shared.u64 t, %1; cvt.u32.u64 %0, t; }" : "=r"(a) : "l"(p));
    return a;
}
__device__ __forceinline__ void cp16(uint32_t dst, const void* src) {
    asm volatile("cp.async.cg.shared.global [%0], [%1], 16;" :: "r"(dst), "l"(src));
}
#define CP_COMMIT()  asm volatile("cp.async.commit_group;" ::: "memory")
#define CP_WAIT(n)   asm volatile("cp.async.wait_group %0;" :: "n"(n) : "memory")

__device__ __forceinline__ void ldsm_x4(uint32_t& r0, uint32_t& r1, uint32_t& r2,
                                        uint32_t& r3, uint32_t addr) {
    asm volatile("ldmatrix.sync.aligned.m8n8.x4.shared.b16 {%0,%1,%2,%3}, [%4];"
                 : "=r"(r0), "=r"(r1), "=r"(r2), "=r"(r3) : "r"(addr));
}
__device__ __forceinline__ void mma16816(float* c, const uint32_t* a,
                                         uint32_t b0, uint32_t b1) {
    asm volatile(
        "mma.sync.aligned.m16n8k16.row.col.f32.f16.f16.f32 "
        "{%0,%1,%2,%3}, {%4,%5,%6,%7}, {%8,%9}, {%0,%1,%2,%3};"
        : "+f"(c[0]), "+f"(c[1]), "+f"(c[2]), "+f"(c[3])
        : "r"(a[0]), "r"(a[1]), "r"(a[2]), "r"(a[3]), "r"(b0), "r"(b1));
}
__device__ __forceinline__ uint32_t cvt_tf32(float v) {
    uint32_t r;
    asm("cvt.rna.tf32.f32 %0, %1;" : "=r"(r) : "f"(v));
    return r;
}
__device__ __forceinline__ void mma_tf32(float* c, const uint32_t* a,
                                         uint32_t b0, uint32_t b1) {
    asm volatile(
        "mma.sync.aligned.m16n8k8.row.col.f32.tf32.tf32.f32 "
        "{%0,%1,%2,%3}, {%4,%5,%6,%7}, {%8,%9}, {%0,%1,%2,%3};"
        : "+f"(c[0]), "+f"(c[1]), "+f"(c[2]), "+f"(c[3])
        : "r"(a[0]), "r"(a[1]), "r"(a[2]), "r"(a[3]), "r"(b0), "r"(b1));
}
#define SW128(off) ((off) ^ (((off) >> 3) & 0x70))

// ---------------------------------------------------------------------------
// Mask dtype handling
// ---------------------------------------------------------------------------
__device__ __forceinline__ bool mask_true(const void* p, long i, int mode)
{
    if (mode == 0) return ((const float*)p)[i] != 0.0f;
    if (mode == 1) return ((const int*)p)[i] != 0;
    if (mode == 2) return ((const unsigned short*)p)[i] != 0;
    return ((const unsigned char*)p)[i] != 0;
}

__global__ void detect_mask_kernel(const void* __restrict__ am)
{
    if (threadIdx.x != 0 || blockIdx.x != 0) return;
    const unsigned int* w = (const unsigned int*)am;
    bool f32ok = true, i32ok = true, bf16ok = true;
    for (int i = 0; i < 1024; i++) {
        unsigned int v = w[i];
        if (!(v == 0u || v == 0x3F800000u)) f32ok = false;
        if (!(v == 0u || v == 1u)) i32ok = false;
        unsigned int h0 = v & 0xFFFFu, h1 = v >> 16;
        if (!((h0 == 0u || h0 == 0x3F80u) && (h1 == 0u || h1 == 0x3F80u))) bf16ok = false;
    }
    g_mask_mode = f32ok ? 0 : (i32ok ? 1 : (bf16ok ? 2 : 3));
}

// ---------------------------------------------------------------------------
// fp32 GEMM (q|k projection, N=64)
// ---------------------------------------------------------------------------
__global__ __launch_bounds__(256) void gemm_f32(
    const float* __restrict__ A, const float* __restrict__ B, float* __restrict__ C,
    int M, int N, int K)
{
    __shared__ float As[16][64];
    __shared__ float Bs[16][64];
    const int tid = threadIdx.x;
    const int m0 = blockIdx.y * 64, n0 = blockIdx.x * 64;
    const int tx = tid & 15, ty = tid >> 4;
    const int arow = tid >> 2, ac = (tid & 3) * 4;
    const int brow = tid >> 4, bc = (tid & 15) * 4;

    float acc[4][4] = {};
    for (int k0 = 0; k0 < K; k0 += 16) {
        float4 av = *(const float4*)(A + (long)(m0 + arow) * K + k0 + ac);
        As[ac + 0][arow] = av.x; As[ac + 1][arow] = av.y;
        As[ac + 2][arow] = av.z; As[ac + 3][arow] = av.w;
        float4 bv = *(const float4*)(B + (long)(k0 + brow) * N + n0 + bc);
        *(float4*)&Bs[brow][bc] = bv;
        __syncthreads();
#pragma unroll
        for (int kk = 0; kk < 16; kk++) {
            float4 a = *(const float4*)&As[kk][ty * 4];
            float4 b = *(const float4*)&Bs[kk][tx * 4];
            acc[0][0] += a.x * b.x; acc[0][1] += a.x * b.y; acc[0][2] += a.x * b.z; acc[0][3] += a.x * b.w;
            acc[1][0] += a.y * b.x; acc[1][1] += a.y * b.y; acc[1][2] += a.y * b.z; acc[1][3] += a.y * b.w;
            acc[2][0] += a.z * b.x; acc[2][1] += a.z * b.y; acc[2][2] += a.z * b.z; acc[2][3] += a.z * b.w;
            acc[3][0] += a.w * b.x; acc[3][1] += a.w * b.y; acc[3][2] += a.w * b.z; acc[3][3] += a.w * b.w;
        }
        __syncthreads();
    }
#pragma unroll
    for (int i = 0; i < 4; i++) {
        const int m = m0 + ty * 4 + i;
#pragma unroll
        for (int j = 0; j < 4; j++)
            C[(long)m * N + n0 + tx * 4 + j] = acc[i][j];
    }
}

// ---------------------------------------------------------------------------
// Converts
// ---------------------------------------------------------------------------
__global__ void conv_x_h_kernel(const float* __restrict__ x)
{
    const long i = ((long)blockIdx.x * blockDim.x + threadIdx.x) * 4;
    float4 v = *(const float4*)(x + i);
    __half o[4] = { __float2half(v.x), __float2half(v.y),
                    __float2half(v.z), __float2half(v.w) };
    *(uint2*)(g_xh + i) = *(uint2*)o;
}

__global__ void concat_wqk_kernel(const float* __restrict__ Wq, const float* __restrict__ Wk)
{
    const int idx = blockIdx.x * blockDim.x + threadIdx.x;
    const int k = idx >> 5, j = idx & 31;
    g_wqk[k * 64 + j]      = Wq[k * 32 + j];
    g_wqk[k * 64 + 32 + j] = Wk[k * 32 + j];
}

__global__ void wtrans_kernel(const float* __restrict__ W, __half* __restrict__ Thi)
{
    __shared__ float tile[32][33];
    const int k0 = blockIdx.y * 32, n0 = blockIdx.x * 32;
    tile[threadIdx.y][threadIdx.x] = W[(long)(k0 + threadIdx.y) * DM + n0 + threadIdx.x];
    __syncthreads();
    const float v = tile[threadIdx.x][threadIdx.y];
    Thi[(long)(n0 + threadIdx.y) * DM + k0 + threadIdx.x] = __float2half(v);
}

// ---------------------------------------------------------------------------
// rowstats: c_i = rowsum(q) * (-1e24) * inv_dk ; pad flag
// ---------------------------------------------------------------------------
__global__ void rowstats_kernel(const void* __restrict__ pad)
{
    const int row = blockIdx.x * blockDim.x + threadIdx.x;
    if (row >= BS_ROWS) return;
    float s = 0.f;
#pragma unroll
    for (int d = 0; d < DK; d++) s += g_qk[row * 64 + d];
    g_crow[row] = s * NINF_F * INV_DK;
    g_padf[row] = mask_true(pad, row, g_mask_mode) ? 1.f : 0.f;
}

// ---------------------------------------------------------------------------
// FLASH attention: scores (tf32) + exact masking + online softmax + P@V,
// fully fused. P never touches global memory: p~ tiles live in SMEM and are
// consumed immediately by fp16 mma against an L2-resident V^T tile.
// Deferred-rescale: O *= exp(m_old - m_new) on max updates; final O *= 1/sum.
// One CTA = 64 queries x DM=512 output; 8 warps.
//   Score phase: wr=wid>>1 (16-q group), wk=wid&1 (64-key half).
//   PV phase:    warp wid owns dm slice [wid*64, wid*64+64).
// SMEM: Q 9K | K dbuf 36K | P~ 64x272B | V 512x272B | stats  -> 201.5 KB
// ---------------------------------------------------------------------------
#define AT_OFF_Q    0           // 64*36*4   = 9216
#define AT_OFF_K    9216        // 2*128*144 = 36864
#define AT_OFF_P    46080       // 64*272    = 17408
#define AT_OFF_V    63488       // 512*272   = 139264
#define AT_OFF_BITS 202752      // 1024
#define AT_OFF_PAD  203776      // 512
#define AT_OFF_CROW 204288      // 256
#define AT_OFF_RMAX 204544      // 256
#define AT_OFF_RSUM 204800      // 256
#define AT_OFF_FSC  205056      // 256
#define AT_OFF_PMAX 205312      // 512
#define AT_OFF_PSUM 205824      // 512
#define AT_SMEM     206336

__global__ __launch_bounds__(256, 1) void attn_flash_kernel(const void* __restrict__ am)
{
    extern __shared__ char dsm[];
    float*    Qs     = (float*)(dsm + AT_OFF_Q);
    float*    KsBase = (float*)(dsm + AT_OFF_K);
    uint32_t* bitsA  = (uint32_t*)(dsm + AT_OFF_BITS);
    uint32_t* padb   = (uint32_t*)(dsm + AT_OFF_PAD);
    float*    crow_s = (float*)(dsm + AT_OFF_CROW);
    float*    rmax_s = (float*)(dsm + AT_OFF_RMAX);
    float*    rsum_s = (float*)(dsm + AT_OFF_RSUM);
    float*    fsc_s  = (float*)(dsm + AT_OFF_FSC);
    float*    pmax_s = (float*)(dsm + AT_OFF_PMAX);
    float*    psum_s = (float*)(dsm + AT_OFF_PSUM);
    const uint32_t sb = smem_u32(dsm);
    const uint32_t Pb = sb + AT_OFF_P;
    const uint32_t Vb = sb + AT_OFF_V;

    const int tid = threadIdx.x;
    const int lane = tid & 31, wid = tid >> 5;
    const int wr = wid >> 1, wk = wid & 1;
    const int b = blockIdx.y;
    const int q0 = blockIdx.x * 64;
    const int mode = g_mask_mode;

    // ---- init ----
#pragma unroll
    for (int it = 0; it < 2; it++) {
        const int i = tid + it * 256;
        const int row = i >> 3, c4 = i & 7;
        *(float4*)(Qs + row * 36 + c4 * 4) =
            *(const float4*)(g_qk + ((long)b * SEQ + q0 + row) * 64 + c4 * 4);
    }
#pragma unroll
    for (int it = 0; it < 16; it++) {
        const int idx = tid + it * 256;
        const bool t = g_padf[(long)b * SEQ + idx] != 0.f;
        const uint32_t bal = __ballot_sync(0xFFFFFFFFu, t);
        if (lane == 0) padb[idx >> 5] = bal;
    }
    if (tid < 64) {
        crow_s[tid] = g_crow[(long)b * SEQ + q0 + tid];
        rmax_s[tid] = -FLT_MAX;
        rsum_s[tid] = 0.f;
    }
    __syncthreads();

    auto load_k = [&](int kt) {
        const int buf = kt & 1;
        const float* src = g_qk + ((long)b * SEQ + kt * 128) * 64 + 32;
        const uint32_t dstb = sb + AT_OFF_K + buf * 18432;
#pragma unroll
        for (int it = 0; it < 4; it++) {
            const int i = tid + it * 256;
            const int row = i >> 3, seg = i & 7;
            cp16(dstb + row * 144 + seg * 16, src + row * 64 + seg * 4);
        }
        CP_COMMIT();
    };
    auto load_v = [&](int kt) {
        const __half* src = g_vt + (long)b * DM * SEQ;
#pragma unroll
        for (int it = 0; it < 32; it++) {
            const int i = tid + it * 256;
            const int row = i >> 4, seg = i & 15;     // dm row, 16B segment
            cp16(Vb + row * 272 + seg * 16, src + (long)row * SEQ + kt * 128 + seg * 8);
        }
        CP_COMMIT();
    };

    float acc[4][8][4] = {};    // [m-block][dm-block][frag] — 128 regs

    load_k(0);
    load_v(0);

    for (int kt = 0; kt < 32; kt++) {
        if (kt + 1 < 32) load_k(kt + 1);

        // attn_mask bits for THIS tile: warp w owns rows w*8..w*8+7
        {
            const long rbase = ((long)b * SEQ + q0 + wid * 8) * SEQ + kt * 128;
#pragma unroll
            for (int rr = 0; rr < 8; rr++) {
#pragma unroll
                for (int cw = 0; cw < 4; cw++) {
                    const bool t = mask_true(am, rbase + (long)rr * SEQ + cw * 32 + lane, mode);
                    const uint32_t bal = __ballot_sync(0xFFFFFFFFu, t);
                    if (lane == 0) bitsA[(wid * 8 + rr) * 4 + cw] = bal;
                }
            }
        }
        // wait for K(kt) (pending after this: V(kt) [+K(kt+1)])
        if (kt + 1 < 32) { CP_WAIT(2); } else { CP_WAIT(1); }
        __syncthreads();

        // ---- score tile (tf32) + exact masking ----
        float s[8][4];
        {
            const float* Kst = KsBase + (kt & 1) * 4608;
#pragma unroll
            for (int nj = 0; nj < 8; nj++) { s[nj][0] = s[nj][1] = s[nj][2] = s[nj][3] = 0.f; }
#pragma unroll
            for (int ks = 0; ks < 4; ks++) {
                const int kb = ks * 8 + (lane & 3);
                uint32_t A[4];
                const int r = wr * 16 + (lane >> 2);
                A[0] = cvt_tf32(Qs[r * 36 + kb]);
                A[1] = cvt_tf32(Qs[(r + 8) * 36 + kb]);
                A[2] = cvt_tf32(Qs[r * 36 + kb + 4]);
                A[3] = cvt_tf32(Qs[(r + 8) * 36 + kb + 4]);
#pragma unroll
                for (int nj = 0; nj < 8; nj++) {
                    const int n = wk * 64 + nj * 8 + (lane >> 2);
                    const uint32_t B0 = cvt_tf32(Kst[n * 36 + kb]);
                    const uint32_t B1 = cvt_tf32(Kst[n * 36 + kb + 4]);
                    mma_tf32(s[nj], A, B0, B1);
                }
            }
            const int r0 = wr * 16 + (lane >> 2), r1 = r0 + 8;
            const float cr0 = crow_s[r0], cr1 = crow_s[r1];
#pragma unroll
            for (int nj = 0; nj < 8; nj++) {
                const int kloc = wk * 64 + nj * 8 + (lane & 3) * 2;     // even
                const uint32_t pw = padb[(kt * 128 + kloc) >> 5];
                const uint32_t w0 = bitsA[r0 * 4 + (kloc >> 5)];
                const uint32_t w1 = bitsA[r1 * 4 + (kloc >> 5)];
                const int sh = kloc & 31;
                float v0 = s[nj][0] * INV_DK, v1 = s[nj][1] * INV_DK;
                float v2 = s[nj][2] * INV_DK, v3 = s[nj][3] * INV_DK;
                if ((pw >> sh) & 1)       { v0 = cr0; v2 = cr1; }
                if ((pw >> (sh + 1)) & 1) { v1 = cr0; v3 = cr1; }
                if ((w0 >> sh) & 1)       v0 = NINF_F;
                if ((w0 >> (sh + 1)) & 1) v1 = NINF_F;
                if ((w1 >> sh) & 1)       v2 = NINF_F;
                if ((w1 >> (sh + 1)) & 1) v3 = NINF_F;
                s[nj][0] = v0; s[nj][1] = v1; s[nj][2] = v2; s[nj][3] = v3;
            }
        }

        // ---- tile max ----
        const int r0 = wr * 16 + (lane >> 2), r1 = r0 + 8;
        float mx0 = -FLT_MAX, mx1 = -FLT_MAX;
#pragma unroll
        for (int nj = 0; nj < 8; nj++) {
            mx0 = fmaxf(mx0, fmaxf(s[nj][0], s[nj][1]));
            mx1 = fmaxf(mx1, fmaxf(s[nj][2], s[nj][3]));
        }
        mx0 = fmaxf(mx0, __shfl_xor_sync(0xFFFFFFFFu, mx0, 1));
        mx0 = fmaxf(mx0, __shfl_xor_sync(0xFFFFFFFFu, mx0, 2));
        mx1 = fmaxf(mx1, __shfl_xor_sync(0xFFFFFFFFu, mx1, 1));
        mx1 = fmaxf(mx1, __shfl_xor_sync(0xFFFFFFFFu, mx1, 2));
        if ((lane & 3) == 0) { pmax_s[r0 * 2 + wk] = mx0; pmax_s[r1 * 2 + wk] = mx1; }
        __syncthreads();

        // ---- combine running stats; record rescale factor ----
        if (tid < 64) {
            const float tm = fmaxf(pmax_s[2 * tid], pmax_s[2 * tid + 1]);
            const float mo = rmax_s[tid];
            const float mn = fmaxf(mo, tm);
            const float f = __expf(mo - mn);
            rsum_s[tid] *= f;
            fsc_s[tid] = f;
            rmax_s[tid] = mn;
            pmax_s[2 * tid] = mn;
        }
        __syncthreads();

        // ---- p~ = exp(s - m_new): partial sums + SMEM P~ tile ----
        const float mn0 = pmax_s[2 * r0], mn1 = pmax_s[2 * r1];
        float sm0 = 0.f, sm1 = 0.f;
#pragma unroll
        for (int nj = 0; nj < 8; nj++) {
            const int kloc = wk * 64 + nj * 8 + (lane & 3) * 2;
            const float e0 = __expf(s[nj][0] - mn0), e1 = __expf(s[nj][1] - mn0);
            const float e2 = __expf(s[nj][2] - mn1), e3 = __expf(s[nj][3] - mn1);
            sm0 += e0 + e1;
            sm1 += e2 + e3;
            *(__half2*)(dsm + AT_OFF_P + r0 * 272 + kloc * 2) = __floats2half2_rn(e0, e1);
            *(__half2*)(dsm + AT_OFF_P + r1 * 272 + kloc * 2) = __floats2half2_rn(e2, e3);
        }
        sm0 += __shfl_xor_sync(0xFFFFFFFFu, sm0, 1);
        sm0 += __shfl_xor_sync(0xFFFFFFFFu, sm0, 2);
        sm1 += __shfl_xor_sync(0xFFFFFFFFu, sm1, 1);
        sm1 += __shfl_xor_sync(0xFFFFFFFFu, sm1, 2);
        if ((lane & 3) == 0) { psum_s[r0 * 2 + wk] = sm0; psum_s[r1 * 2 + wk] = sm1; }
        __syncthreads();
        if (tid < 64) rsum_s[tid] += psum_s[2 * tid] + psum_s[2 * tid + 1];

        // wait for V(kt), make P~ visible
        if (kt + 1 < 32) { CP_WAIT(1); } else { CP_WAIT(0); }
        __syncthreads();

        // ---- PV phase: O = O*f + P~ @ V  (warp owns dm slice wid*64..+64) ----
#pragma unroll
        for (int mi = 0; mi < 4; mi++) {
            const float f0 = fsc_s[mi * 16 + (lane >> 2)];
            const float f1 = fsc_s[mi * 16 + 8 + (lane >> 2)];
#pragma unroll
            for (int nj = 0; nj < 8; nj++) {
                acc[mi][nj][0] *= f0; acc[mi][nj][1] *= f0;
                acc[mi][nj][2] *= f1; acc[mi][nj][3] *= f1;
            }
        }
#pragma unroll
        for (int ks = 0; ks < 8; ks++) {
            uint32_t a[4][4];
#pragma unroll
            for (int mi = 0; mi < 4; mi++) {
                const int row = mi * 16 + (lane & 15);
                ldsm_x4(a[mi][0], a[mi][1], a[mi][2], a[mi][3],
                        Pb + row * 272 + ks * 32 + ((lane >> 4) << 4));
            }
            uint32_t bf[4][4];
#pragma unroll
            for (int j = 0; j < 4; j++) {
                const int vr = wid * 64 + j * 16 + (lane & 7) + ((lane >> 4) << 3);
                ldsm_x4(bf[j][0], bf[j][1], bf[j][2], bf[j][3],
                        Vb + vr * 272 + ks * 32 + (((lane >> 3) & 1) << 4));
            }
#pragma unroll
            for (int mi = 0; mi < 4; mi++)
#pragma unroll
                for (int nj = 0; nj < 8; nj++)
                    mma16816(acc[mi][nj], a[mi],
                             bf[nj >> 1][(nj & 1) * 2], bf[nj >> 1][(nj & 1) * 2 + 1]);
        }
        __syncthreads();                         // all warps done with V / P~
        if (kt + 1 < 32) load_v(kt + 1);         // prefetch next V under scores
    }

    // ---- epilogue: O *= 1/sum, write h fp32 ----
#pragma unroll
    for (int mi = 0; mi < 4; mi++) {
        const int r0 = mi * 16 + (lane >> 2), r1 = r0 + 8;
        const float i0 = 1.f / rsum_s[r0];
        const float i1 = 1.f / rsum_s[r1];
        const long g0 = ((long)b * SEQ + q0 + r0) * DM + wid * 64;
        const long g1 = ((long)b * SEQ + q0 + r1) * DM + wid * 64;
#pragma unroll
        for (int nj = 0; nj < 8; nj++) {
            const int cl = nj * 8 + (lane & 3) * 2;
            *(float2*)(g_h + g0 + cl) = make_float2(acc[mi][nj][0] * i0, acc[mi][nj][1] * i0);
            *(float2*)(g_h + g1 + cl) = make_float2(acc[mi][nj][2] * i1, acc[mi][nj][3] * i1);
        }
    }
}

// ---------------------------------------------------------------------------
// out = LayerNorm(A + B); optionally emit fp16 hi/lo split of out
// ---------------------------------------------------------------------------
__global__ __launch_bounds__(128) void add_ln_kernel(
    const float* __restrict__ A, const float* __restrict__ Bv,
    const float* __restrict__ g, const float* __restrict__ be,
    float* __restrict__ out, __half* __restrict__ ohi, __half* __restrict__ olo)
{
    const long row = blockIdx.x;
    const int tid = threadIdx.x;
    const int lane = tid & 31, wid = tid >> 5;
    __shared__ float red[4];

    float4 a = *(const float4*)(A + row * DM + tid * 4);
    float4 b = *(const float4*)(Bv + row * DM + tid * 4);
    float x0 = a.x + b.x, x1 = a.y + b.y, x2 = a.z + b.z, x3 = a.w + b.w;

    float s = x0 + x1 + x2 + x3;
#pragma unroll
    for (int o = 16; o > 0; o >>= 1) s += __shfl_xor_sync(0xFFFFFFFFu, s, o);
    if (lane == 0) red[wid] = s;
    __syncthreads();
    s = red[0] + red[1] + red[2] + red[3];
    const float mu = s * (1.0f / DM);
    __syncthreads();

    const float d0 = x0 - mu, d1 = x1 - mu, d2 = x2 - mu, d3 = x3 - mu;
    float vs = d0 * d0 + d1 * d1 + d2 * d2 + d3 * d3;
#pragma unroll
    for (int o = 16; o > 0; o >>= 1) vs += __shfl_xor_sync(0xFFFFFFFFu, vs, o);
    if (lane == 0) red[wid] = vs;
    __syncthreads();
    vs = red[0] + red[1] + red[2] + red[3];
    const float rs = rsqrtf(vs * (1.0f / DM) + 1e-5f);

    float4 gg = *(const float4*)(g + tid * 4);
    float4 bb = *(const float4*)(be + tid * 4);
    float o4[4];
    o4[0] = d0 * rs * gg.x + bb.x;
    o4[1] = d1 * rs * gg.y + bb.y;
    o4[2] = d2 * rs * gg.z + bb.z;
    o4[3] = d3 * rs * gg.w + bb.w;
    *(float4*)(out + row * DM + tid * 4) = *(float4*)o4;
    if (ohi) {
        __half hi[4], lo[4];
#pragma unroll
        for (int j = 0; j < 4; j++) {
            hi[j] = __float2half(o4[j]);
            lo[j] = __float2half(o4[j] - __half2float(hi[j]));
        }
        *(uint2*)(ohi + row * DM + tid * 4) = *(uint2*)hi;
        *(uint2*)(olo + row * DM + tid * 4) = *(uint2*)lo;
    }
}

// ---------------------------------------------------------------------------
// fp16 tensor-core GEMM via mma.sync — 3-stage cp.async pipeline.
//   C[m][n] = sum_p sum_k Ap[m][k] * Bp[n][k]
// BM=BN=128, BK=64, 8 warps (64x32 warp tiles), SW128 swizzle, fp32 accum.
// mode 1: fp16 transposed (Vt)   mode 2: bias+leaky fp32
// ---------------------------------------------------------------------------
#define GM_STAGE 32768
#define GM_SMEM  (3 * GM_STAGE)      // 96 KB

__global__ __launch_bounds__(256) void gemm_mma(
    const __half* __restrict__ A0, const __half* __restrict__ A1,
    const __half* __restrict__ B0, const __half* __restrict__ B1,
    int npass, int Ktot,
    float* __restrict__ C, __half* __restrict__ Ct,
    const float* __restrict__ bias, int mode, int ldc)
{
    extern __shared__ char smem[];
    const uint32_t sb = smem_u32(smem);
    const int tid = threadIdx.x;
    const int lane = tid & 31, wid = tid >> 5;
    const int wr = wid >> 2, wc = wid & 3;
    const int m0 = blockIdx.y * 128, n0 = blockIdx.x * 128;

    const __half* Ap[2] = { A0, A1 };
    const __half* Bp[2] = { B0, B1 };

    const int kc = Ktot >> 6;
    const int nch = npass * kc;
    const int lrow = tid >> 3, lc = (tid & 7);

    auto load_chunk = [&](int c) {
        const int buf = c % 3;
        const int p = c / kc;
        const int k0 = (c - p * kc) << 6;
        const __half* A = Ap[p];
        const __half* B = Bp[p];
        const uint32_t sa = sb + buf * GM_STAGE;
        const uint32_t sbB = sa + 16384;
#pragma unroll
        for (int it = 0; it < 4; it++) {
            const int row = lrow + it * 32;
            cp16(sa + SW128(row * 128 + lc * 16), A + (long)(m0 + row) * Ktot + k0 + lc * 8);
            cp16(sbB + SW128(row * 128 + lc * 16), B + (long)(n0 + row) * Ktot + k0 + lc * 8);
        }
        CP_COMMIT();
    };

    float acc[4][4][4] = {};

    load_chunk(0);
    if (nch > 1) load_chunk(1);
    for (int c = 0; c < nch; c++) {
        if (c + 2 < nch) { load_chunk(c + 2); CP_WAIT(2); }
        else if (c + 1 < nch) { CP_WAIT(1); }
        else { CP_WAIT(0); }
        __syncthreads();

        const uint32_t sa = sb + (c % 3) * GM_STAGE;
        const uint32_t sbB = sa + 16384;
#pragma unroll
        for (int ks = 0; ks < 4; ks++) {
            uint32_t a[4][4];
#pragma unroll
            for (int mi = 0; mi < 4; mi++) {
                const int mr = wr * 64 + mi * 16 + (lane & 15);
                ldsm_x4(a[mi][0], a[mi][1], a[mi][2], a[mi][3],
                        sa + SW128(mr * 128 + ks * 32 + ((lane >> 4) << 4)));
            }
            uint32_t b[2][4];
#pragma unroll
            for (int j = 0; j < 2; j++) {
                const int nr = wc * 32 + j * 16 + (lane & 7) + ((lane >> 4) << 3);
                ldsm_x4(b[j][0], b[j][1], b[j][2], b[j][3],
                        sbB + SW128(nr * 128 + ks * 32 + (((lane >> 3) & 1) << 4)));
            }
#pragma unroll
            for (int mi = 0; mi < 4; mi++)
#pragma unroll
                for (int nj = 0; nj < 4; nj++)
                    mma16816(acc[mi][nj], a[mi],
                             b[nj >> 1][(nj & 1) * 2], b[nj >> 1][(nj & 1) * 2 + 1]);
        }
        __syncthreads();
    }

    const int crow = lane >> 2, ccol = (lane & 3) * 2;
    if (mode == 1) {
        __half* st = (__half*)smem;
#pragma unroll
        for (int mi = 0; mi < 4; mi++) {
#pragma unroll
            for (int nj = 0; nj < 4; nj++) {
                const int ml = wr * 64 + mi * 16 + crow;
                const int cl = wc * 32 + nj * 8 + ccol;
                st[(cl + 0) * 128 + ml]     = __float2half(acc[mi][nj][0]);
                st[(cl + 1) * 128 + ml]     = __float2half(acc[mi][nj][1]);
                st[(cl + 0) * 128 + ml + 8] = __float2half(acc[mi][nj][2]);
                st[(cl + 1) * 128 + ml + 8] = __float2half(acc[mi][nj][3]);
            }
        }
        __syncthreads();
        const long bb = m0 >> 12;
        const long s0 = m0 & 4095;
#pragma unroll
        for (int it = 0; it < 8; it++) {
            const int i = tid + it * 256;
            const int row = i >> 4, seg = i & 15;
            *(uint4*)(Ct + ((bb * DM) + n0 + row) * SEQ + s0 + seg * 8) =
                *(uint4*)(st + row * 128 + seg * 8);
        }
    } else {
#pragma unroll
        for (int mi = 0; mi < 4; mi++) {
#pragma unroll
            for (int nj = 0; nj < 4; nj++) {
                const long mr = m0 + wr * 64 + mi * 16 + crow;
                const int cl = n0 + wc * 32 + nj * 8 + ccol;
                const float b0 = bias[cl], b1 = bias[cl + 1];
                float v0 = acc[mi][nj][0] + b0, v1 = acc[mi][nj][1] + b1;
                float v2 = acc[mi][nj][2] + b0, v3 = acc[mi][nj][3] + b1;
                v0 = (v0 > 0.f) ? v0 : 0.01f * v0;
                v1 = (v1 > 0.f) ? v1 : 0.01f * v1;
                v2 = (v2 > 0.f) ? v2 : 0.01f * v2;
                v3 = (v3 > 0.f) ? v3 : 0.01f * v3;
                *(float2*)(C + mr * ldc + cl)       = make_float2(v0, v1);
                *(float2*)(C + (mr + 8) * ldc + cl) = make_float2(v2, v3);
            }
        }
    }
}

// ---------------------------------------------------------------------------
// Host launcher
// ---------------------------------------------------------------------------
extern "C" void kernel_launch(void* const* d_in, const int* in_sizes, int n_in,
                              void* d_out, int out_size)
{
    const float* x   = (const float*)d_in[0];
    const void*  am  = d_in[1];
    const void*  kpm = d_in[2];
    const float* Wq  = (const float*)d_in[3];
    const float* Wk  = (const float*)d_in[4];
    const float* Wv  = (const float*)d_in[5];
    const float* Wf  = (const float*)d_in[6];
    const float* bfp = (const float*)d_in[7];
    const float* g1  = (const float*)d_in[8];
    const float* b1  = (const float*)d_in[9];
    const float* g2  = (const float*)d_in[10];
    const float* b2  = (const float*)d_in[11];
    float* out = (float*)d_out;

    void *ph, *pz, *pxh, *pvt, *pzhi, *pzlo, *pwqk, *pwvt, *pwfhi, *pqk;
    cudaGetSymbolAddress(&pqk, g_qk);
    cudaGetSymbolAddress(&ph, g_h);
    cudaGetSymbolAddress(&pz, g_z);
    cudaGetSymbolAddress(&pxh, g_xh);
    cudaGetSymbolAddress(&pvt, g_vt);
    cudaGetSymbolAddress(&pzhi, g_zhi);
    cudaGetSymbolAddress(&pzlo, g_zlo);
    cudaGetSymbolAddress(&pwqk, g_wqk);
    cudaGetSymbolAddress(&pwvt, g_wvt);
    cudaGetSymbolAddress(&pwfhi, g_wfhi);

    cudaFuncSetAttribute(gemm_mma, cudaFuncAttributeMaxDynamicSharedMemorySize, GM_SMEM);
    cudaFuncSetAttribute(attn_flash_kernel, cudaFuncAttributeMaxDynamicSharedMemorySize, AT_SMEM);

    // 0) mask detection + converts
    detect_mask_kernel<<<1, 32>>>(am);
    conv_x_h_kernel<<<(BS_ROWS * DM) / (256 * 4), 256>>>(x);
    concat_wqk_kernel<<<(DM * 32) / 256, 256>>>(Wq, Wk);
    wtrans_kernel<<<dim3(16, 16), dim3(32, 32)>>>(Wv, (__half*)pwvt);
    wtrans_kernel<<<dim3(16, 16), dim3(32, 32)>>>(Wf, (__half*)pwfhi);

    // 1) q|k projection (fp32, protects the sign(rowsum(q)) knife edge)
    gemm_f32<<<dim3(1, BS_ROWS / 64), 256>>>(x, (const float*)pwqk, (float*)pqk,
                                             BS_ROWS, 64, DM);
    rowstats_kernel<<<BS_ROWS / 256, 256>>>(kpm);

    // 2) Vt = (x @ Wv)^T fp16 (tensor cores, transposed store)
    gemm_mma<<<dim3(DM / 128, BS_ROWS / 128, 1), 256, GM_SMEM>>>(
        (const __half*)pxh, nullptr, (const __half*)pwvt, nullptr,
        1, DM, nullptr, (__half*)pvt, nullptr, 1, 0);

    // 3) FLASH: scores + mask + softmax + P@V in one kernel -> h fp32
    attn_flash_kernel<<<dim3(SEQ / 64, BATCH), 256, AT_SMEM>>>(am);

    // 4) z = LN(x + h), emit fp16 hi/lo split
    add_ln_kernel<<<BS_ROWS, 128>>>(x, (const float*)ph, g1, b1, (float*)pz,
                                    (__half*)pzhi, (__half*)pzlo);

    // 5) y = leaky(z @ Wf + bf) via 2-pass split-fp16 (zhi + zlo vs Wf_hi)
    gemm_mma<<<dim3(DM / 128, BS_ROWS / 128, 1), 256, GM_SMEM>>>(
        (const __half*)pzhi, (const __half*)pzlo,
        (const __half*)pwfhi, (const __half*)pwfhi,
        2, DM, (float*)ph, nullptr, bfp, 2, DM);

    // 6) out = LN(z + y)
    add_ln_kernel<<<BS_ROWS, 128>>>((const float*)pz, (const float*)ph, g2, b2, out,
                                    nullptr, nullptr);
}

// round 15
// speedup vs baseline: 1.2456x; 1.2456x over previous
#include <cuda_runtime.h>
#include <cuda_fp16.h>
#include <cstdint>
#include <cfloat>

// ---------------------------------------------------------------------------
// Problem constants
// ---------------------------------------------------------------------------
#define BATCH 4
#define SEQ   4096
#define DM    512
#define DK    32
#define BS_ROWS (BATCH * SEQ)           // 16384
static const float INV_DK = 0.17677669529663687f;   // 1/sqrt(32)
#define NINF_F (-1e24f)

// ---------------------------------------------------------------------------
// Scratch (static device globals; allocations are forbidden)
// ---------------------------------------------------------------------------
static __device__ int      g_mask_mode;
static __device__ float    g_qk[BS_ROWS * 64];                   // q | k
static __device__ float    g_crow[BS_ROWS];
static __device__ float    g_padf[BS_ROWS];
static __device__ float    g_h[(size_t)BS_ROWS * DM];            // 32 MB
static __device__ float    g_z[(size_t)BS_ROWS * DM];            // 32 MB
static __device__ __half   g_p[(size_t)BATCH * SEQ * SEQ];       // 128 MB probs
static __device__ __half   g_xh[(size_t)BS_ROWS * DM];           // x fp16
static __device__ __half   g_vt[(size_t)BATCH * DM * SEQ];       // V^T fp16
static __device__ __half   g_zhi[(size_t)BS_ROWS * DM];
static __device__ __half   g_zlo[(size_t)BS_ROWS * DM];
static __device__ float    g_wqk[DM * 64];                       // Wq|Wk fp32
static __device__ __half   g_wvt[DM * DM];
static __device__ __half   g_wfhi[DM * DM];

// ---------------------------------------------------------------------------
// PTX helpers (generic compute_103 safe)
// ---------------------------------------------------------------------------
__device__ __forceinline__ uint32_t smem_u32(const void* p) {
    uint32_t a;
    asm("{ .reg .u64 t; cvta.to.shared.u64 t, %1; cvt.u32.u64 %0, t; }" : "=r"(a) : "l"(p));
    return a;
}
__device__ __forceinline__ void cp16(uint32_t dst, const void* src) {
    asm volatile("cp.async.cg.shared.global [%0], [%1], 16;" :: "r"(dst), "l"(src));
}
#define CP_COMMIT()  asm volatile("cp.async.commit_group;" ::: "memory")
#define CP_WAIT(n)   asm volatile("cp.async.wait_group %0;" :: "n"(n) : "memory")

__device__ __forceinline__ void ldsm_x4(uint32_t& r0, uint32_t& r1, uint32_t& r2,
                                        uint32_t& r3, uint32_t addr) {
    asm volatile("ldmatrix.sync.aligned.m8n8.x4.shared.b16 {%0,%1,%2,%3}, [%4];"
                 : "=r"(r0), "=r"(r1), "=r"(r2), "=r"(r3) : "r"(addr));
}
__device__ __forceinline__ void mma16816(float* c, const uint32_t* a,
                                         uint32_t b0, uint32_t b1) {
    asm volatile(
        "mma.sync.aligned.m16n8k16.row.col.f32.f16.f16.f32 "
        "{%0,%1,%2,%3}, {%4,%5,%6,%7}, {%8,%9}, {%0,%1,%2,%3};"
        : "+f"(c[0]), "+f"(c[1]), "+f"(c[2]), "+f"(c[3])
        : "r"(a[0]), "r"(a[1]), "r"(a[2]), "r"(a[3]), "r"(b0), "r"(b1));
}
__device__ __forceinline__ uint32_t cvt_tf32(float v) {
    uint32_t r;
    asm("cvt.rna.tf32.f32 %0, %1;" : "=r"(r) : "f"(v));
    return r;
}
__device__ __forceinline__ void mma_tf32(float* c, const uint32_t* a,
                                         uint32_t b0, uint32_t b1) {
    asm volatile(
        "mma.sync.aligned.m16n8k8.row.col.f32.tf32.tf32.f32 "
        "{%0,%1,%2,%3}, {%4,%5,%6,%7}, {%8,%9}, {%0,%1,%2,%3};"
        : "+f"(c[0]), "+f"(c[1]), "+f"(c[2]), "+f"(c[3])
        : "r"(a[0]), "r"(a[1]), "r"(a[2]), "r"(a[3]), "r"(b0), "r"(b1));
}
#define SW128(off) ((off) ^ (((off) >> 3) & 0x70))

// ---------------------------------------------------------------------------
// Mask dtype handling
// ---------------------------------------------------------------------------
__device__ __forceinline__ bool mask_true(const void* p, long i, int mode)
{
    if (mode == 0) return ((const float*)p)[i] != 0.0f;
    if (mode == 1) return ((const int*)p)[i] != 0;
    if (mode == 2) return ((const unsigned short*)p)[i] != 0;
    return ((const unsigned char*)p)[i] != 0;
}

__global__ void detect_mask_kernel(const void* __restrict__ am)
{
    if (threadIdx.x != 0 || blockIdx.x != 0) return;
    const unsigned int* w = (const unsigned int*)am;
    bool f32ok = true, i32ok = true, bf16ok = true;
    for (int i = 0; i < 1024; i++) {
        unsigned int v = w[i];
        if (!(v == 0u || v == 0x3F800000u)) f32ok = false;
        if (!(v == 0u || v == 1u)) i32ok = false;
        unsigned int h0 = v & 0xFFFFu, h1 = v >> 16;
        if (!((h0 == 0u || h0 == 0x3F80u) && (h1 == 0u || h1 == 0x3F80u))) bf16ok = false;
    }
    g_mask_mode = f32ok ? 0 : (i32ok ? 1 : (bf16ok ? 2 : 3));
}

// ---------------------------------------------------------------------------
// fp32 GEMM (q|k projection, N=64)
// ---------------------------------------------------------------------------
__global__ __launch_bounds__(256) void gemm_f32(
    const float* __restrict__ A, const float* __restrict__ B, float* __restrict__ C,
    int M, int N, int K)
{
    __shared__ float As[16][64];
    __shared__ float Bs[16][64];
    const int tid = threadIdx.x;
    const int m0 = blockIdx.y * 64, n0 = blockIdx.x * 64;
    const int tx = tid & 15, ty = tid >> 4;
    const int arow = tid >> 2, ac = (tid & 3) * 4;
    const int brow = tid >> 4, bc = (tid & 15) * 4;

    float acc[4][4] = {};
    for (int k0 = 0; k0 < K; k0 += 16) {
        float4 av = *(const float4*)(A + (long)(m0 + arow) * K + k0 + ac);
        As[ac + 0][arow] = av.x; As[ac + 1][arow] = av.y;
        As[ac + 2][arow] = av.z; As[ac + 3][arow] = av.w;
        float4 bv = *(const float4*)(B + (long)(k0 + brow) * N + n0 + bc);
        *(float4*)&Bs[brow][bc] = bv;
        __syncthreads();
#pragma unroll
        for (int kk = 0; kk < 16; kk++) {
            float4 a = *(const float4*)&As[kk][ty * 4];
            float4 b = *(const float4*)&Bs[kk][tx * 4];
            acc[0][0] += a.x * b.x; acc[0][1] += a.x * b.y; acc[0][2] += a.x * b.z; acc[0][3] += a.x * b.w;
            acc[1][0] += a.y * b.x; acc[1][1] += a.y * b.y; acc[1][2] += a.y * b.z; acc[1][3] += a.y * b.w;
            acc[2][0] += a.z * b.x; acc[2][1] += a.z * b.y; acc[2][2] += a.z * b.z; acc[2][3] += a.z * b.w;
            acc[3][0] += a.w * b.x; acc[3][1] += a.w * b.y; acc[3][2] += a.w * b.z; acc[3][3] += a.w * b.w;
        }
        __syncthreads();
    }
#pragma unroll
    for (int i = 0; i < 4; i++) {
        const int m = m0 + ty * 4 + i;
#pragma unroll
        for (int j = 0; j < 4; j++)
            C[(long)m * N + n0 + tx * 4 + j] = acc[i][j];
    }
}

// ---------------------------------------------------------------------------
// Converts
// ---------------------------------------------------------------------------
__global__ void conv_x_h_kernel(const float* __restrict__ x)
{
    const long i = ((long)blockIdx.x * blockDim.x + threadIdx.x) * 4;
    float4 v = *(const float4*)(x + i);
    __half o[4] = { __float2half(v.x), __float2half(v.y),
                    __float2half(v.z), __float2half(v.w) };
    *(uint2*)(g_xh + i) = *(uint2*)o;
}

__global__ void concat_wqk_kernel(const float* __restrict__ Wq, const float* __restrict__ Wk)
{
    const int idx = blockIdx.x * blockDim.x + threadIdx.x;
    const int k = idx >> 5, j = idx & 31;
    g_wqk[k * 64 + j]      = Wq[k * 32 + j];
    g_wqk[k * 64 + 32 + j] = Wk[k * 32 + j];
}

__global__ void wtrans_kernel(const float* __restrict__ W, __half* __restrict__ Thi)
{
    __shared__ float tile[32][33];
    const int k0 = blockIdx.y * 32, n0 = blockIdx.x * 32;
    tile[threadIdx.y][threadIdx.x] = W[(long)(k0 + threadIdx.y) * DM + n0 + threadIdx.x];
    __syncthreads();
    const float v = tile[threadIdx.x][threadIdx.y];
    Thi[(long)(n0 + threadIdx.y) * DM + k0 + threadIdx.x] = __float2half(v);
}

// ---------------------------------------------------------------------------
// rowstats: c_i = rowsum(q) * (-1e24) * inv_dk ; pad flag
// ---------------------------------------------------------------------------
__global__ void rowstats_kernel(const void* __restrict__ pad)
{
    const int row = blockIdx.x * blockDim.x + threadIdx.x;
    if (row >= BS_ROWS) return;
    float s = 0.f;
#pragma unroll
    for (int d = 0; d < DK; d++) s += g_qk[row * 64 + d];
    g_crow[row] = s * NINF_F * INV_DK;
    g_padf[row] = mask_true(pad, row, g_mask_mode) ? 1.f : 0.f;
}

// ---------------------------------------------------------------------------
// SINGLE-PASS fused attention + in-CTA tail normalization (round-10 design).
// ---------------------------------------------------------------------------
#define AT_OFF_Q    0          // 64*36*4  = 9216
#define AT_OFF_K    9216       // 2*128*144 = 36864
#define AT_OFF_BITS 46080      // 64*4*4 = 1024 (current tile only)
#define AT_OFF_PAD  47104      // 128*4 = 512
#define AT_OFF_CROW 47616      // 64*4
#define AT_OFF_RMAX 47872
#define AT_OFF_RSUM 48128
#define AT_OFF_PMAX 48384      // 128*4
#define AT_OFF_PSUM 48896      // 128*4
#define AT_OFF_TMX  49408      // 32*64*4 = 8192  (layout [kt*64 + row])
#define AT_SMEM     57600

__global__ __launch_bounds__(256) void attn_probs_kernel(const void* __restrict__ am)
{
    extern __shared__ char dsm[];
    float*    Qs     = (float*)(dsm + AT_OFF_Q);
    float*    KsBase = (float*)(dsm + AT_OFF_K);
    uint32_t* bitsA  = (uint32_t*)(dsm + AT_OFF_BITS);
    uint32_t* padb   = (uint32_t*)(dsm + AT_OFF_PAD);
    float*    crow_s = (float*)(dsm + AT_OFF_CROW);
    float*    rmax_s = (float*)(dsm + AT_OFF_RMAX);
    float*    rsum_s = (float*)(dsm + AT_OFF_RSUM);
    float*    pmax_s = (float*)(dsm + AT_OFF_PMAX);
    float*    psum_s = (float*)(dsm + AT_OFF_PSUM);
    float*    tmx_s  = (float*)(dsm + AT_OFF_TMX);
    const uint32_t sb = smem_u32(dsm);

    const int tid = threadIdx.x;
    const int lane = tid & 31, wid = tid >> 5;
    const int wr = wid >> 1, wk = wid & 1;
    const int b = blockIdx.y;
    const int q0 = blockIdx.x * 64;
    const int mode = g_mask_mode;

    // ---- init ----
#pragma unroll
    for (int it = 0; it < 2; it++) {
        const int i = tid + it * 256;
        const int row = i >> 3, c4 = i & 7;
        *(float4*)(Qs + row * 36 + c4 * 4) =
            *(const float4*)(g_qk + ((long)b * SEQ + q0 + row) * 64 + c4 * 4);
    }
#pragma unroll
    for (int it = 0; it < 16; it++) {
        const int idx = tid + it * 256;
        const bool t = g_padf[(long)b * SEQ + idx] != 0.f;
        const uint32_t bal = __ballot_sync(0xFFFFFFFFu, t);
        if (lane == 0) padb[idx >> 5] = bal;
    }
    if (tid < 64) {
        crow_s[tid] = g_crow[(long)b * SEQ + q0 + tid];
        rmax_s[tid] = -FLT_MAX;
        rsum_s[tid] = 0.f;
    }
    __syncthreads();

    auto load_k = [&](int kt) {
        const int buf = kt & 1;
        const float* src = g_qk + ((long)b * SEQ + kt * 128) * 64 + 32;
        const uint32_t dstb = sb + AT_OFF_K + buf * 18432;
#pragma unroll
        for (int it = 0; it < 4; it++) {
            const int i = tid + it * 256;
            const int row = i >> 3, seg = i & 7;
            cp16(dstb + row * 144 + seg * 16, src + row * 64 + seg * 4);
        }
        CP_COMMIT();
    };

    load_k(0);
    for (int kt = 0; kt < 32; kt++) {
        if (kt + 1 < 32) load_k(kt + 1);

        // attn_mask bits for THIS tile: warp w owns rows w*8..w*8+7
        {
            const long rbase = ((long)b * SEQ + q0 + wid * 8) * SEQ + kt * 128;
#pragma unroll
            for (int rr = 0; rr < 8; rr++) {
#pragma unroll
                for (int cw = 0; cw < 4; cw++) {
                    const bool t = mask_true(am, rbase + (long)rr * SEQ + cw * 32 + lane, mode);
                    const uint32_t bal = __ballot_sync(0xFFFFFFFFu, t);
                    if (lane == 0) bitsA[(wid * 8 + rr) * 4 + cw] = bal;
                }
            }
        }
        if (kt + 1 < 32) { CP_WAIT(1); } else { CP_WAIT(0); }
        __syncthreads();

        // ---- score tile (tf32) + exact masking ----
        float s[8][4];
        {
            const float* Kst = KsBase + (kt & 1) * 4608;
#pragma unroll
            for (int nj = 0; nj < 8; nj++) { s[nj][0] = s[nj][1] = s[nj][2] = s[nj][3] = 0.f; }
#pragma unroll
            for (int ks = 0; ks < 4; ks++) {
                const int kb = ks * 8 + (lane & 3);
                uint32_t A[4];
                const int r = wr * 16 + (lane >> 2);
                A[0] = cvt_tf32(Qs[r * 36 + kb]);
                A[1] = cvt_tf32(Qs[(r + 8) * 36 + kb]);
                A[2] = cvt_tf32(Qs[r * 36 + kb + 4]);
                A[3] = cvt_tf32(Qs[(r + 8) * 36 + kb + 4]);
#pragma unroll
                for (int nj = 0; nj < 8; nj++) {
                    const int n = wk * 64 + nj * 8 + (lane >> 2);
                    const uint32_t B0 = cvt_tf32(Kst[n * 36 + kb]);
                    const uint32_t B1 = cvt_tf32(Kst[n * 36 + kb + 4]);
                    mma_tf32(s[nj], A, B0, B1);
                }
            }
            const int r0 = wr * 16 + (lane >> 2), r1 = r0 + 8;
            const float cr0 = crow_s[r0], cr1 = crow_s[r1];
#pragma unroll
            for (int nj = 0; nj < 8; nj++) {
                const int kloc = wk * 64 + nj * 8 + (lane & 3) * 2;     // even
                const uint32_t pw = padb[(kt * 128 + kloc) >> 5];
                const uint32_t w0 = bitsA[r0 * 4 + (kloc >> 5)];
                const uint32_t w1 = bitsA[r1 * 4 + (kloc >> 5)];
                const int sh = kloc & 31;
                float v0 = s[nj][0] * INV_DK, v1 = s[nj][1] * INV_DK;
                float v2 = s[nj][2] * INV_DK, v3 = s[nj][3] * INV_DK;
                if ((pw >> sh) & 1)       { v0 = cr0; v2 = cr1; }
                if ((pw >> (sh + 1)) & 1) { v1 = cr0; v3 = cr1; }
                if ((w0 >> sh) & 1)       v0 = NINF_F;
                if ((w0 >> (sh + 1)) & 1) v1 = NINF_F;
                if ((w1 >> sh) & 1)       v2 = NINF_F;
                if ((w1 >> (sh + 1)) & 1) v3 = NINF_F;
                s[nj][0] = v0; s[nj][1] = v1; s[nj][2] = v2; s[nj][3] = v3;
            }
        }

        // ---- tile max ----
        const int r0 = wr * 16 + (lane >> 2), r1 = r0 + 8;
        float mx0 = -FLT_MAX, mx1 = -FLT_MAX;
#pragma unroll
        for (int nj = 0; nj < 8; nj++) {
            mx0 = fmaxf(mx0, fmaxf(s[nj][0], s[nj][1]));
            mx1 = fmaxf(mx1, fmaxf(s[nj][2], s[nj][3]));
        }
        mx0 = fmaxf(mx0, __shfl_xor_sync(0xFFFFFFFFu, mx0, 1));
        mx0 = fmaxf(mx0, __shfl_xor_sync(0xFFFFFFFFu, mx0, 2));
        mx1 = fmaxf(mx1, __shfl_xor_sync(0xFFFFFFFFu, mx1, 1));
        mx1 = fmaxf(mx1, __shfl_xor_sync(0xFFFFFFFFu, mx1, 2));
        if ((lane & 3) == 0) { pmax_s[r0 * 2 + wk] = mx0; pmax_s[r1 * 2 + wk] = mx1; }
        __syncthreads();

        // ---- combine running stats; record m_kt in SMEM ----
        if (tid < 64) {
            const float tm = fmaxf(pmax_s[2 * tid], pmax_s[2 * tid + 1]);
            const float mo = rmax_s[tid];
            const float mn = fmaxf(mo, tm);
            rsum_s[tid] *= __expf(mo - mn);
            rmax_s[tid] = mn;
            pmax_s[2 * tid] = mn;
            tmx_s[kt * 64 + tid] = mn;
        }
        __syncthreads();

        // ---- p~ = exp(s - m_kt): accumulate sum AND store fp16 ----
        const float mn0 = pmax_s[2 * r0], mn1 = pmax_s[2 * r1];
        const long gr0 = ((long)b * SEQ + q0 + r0) * SEQ;
        const long gr1 = ((long)b * SEQ + q0 + r1) * SEQ;
        float sm0 = 0.f, sm1 = 0.f;
#pragma unroll
        for (int nj = 0; nj < 8; nj++) {
            const int kk = kt * 128 + wk * 64 + nj * 8 + (lane & 3) * 2;
            const float e0 = __expf(s[nj][0] - mn0), e1 = __expf(s[nj][1] - mn0);
            const float e2 = __expf(s[nj][2] - mn1), e3 = __expf(s[nj][3] - mn1);
            sm0 += e0 + e1;
            sm1 += e2 + e3;
            *(__half2*)(g_p + gr0 + kk) = __floats2half2_rn(e0, e1);
            *(__half2*)(g_p + gr1 + kk) = __floats2half2_rn(e2, e3);
        }
        sm0 += __shfl_xor_sync(0xFFFFFFFFu, sm0, 1);
        sm0 += __shfl_xor_sync(0xFFFFFFFFu, sm0, 2);
        sm1 += __shfl_xor_sync(0xFFFFFFFFu, sm1, 1);
        sm1 += __shfl_xor_sync(0xFFFFFFFFu, sm1, 2);
        if ((lane & 3) == 0) { psum_s[r0 * 2 + wk] = sm0; psum_s[r1 * 2 + wk] = sm1; }
        __syncthreads();
        if (tid < 64) rsum_s[tid] += psum_s[2 * tid] + psum_s[2 * tid + 1];
        __syncthreads();
    }

    // ---- tail: w[kt][row] = exp(m_kt - m_fin) / sum  (in place in tmx_s) ----
#pragma unroll
    for (int j = 0; j < 8; j++) {
        const int i = tid + j * 256;            // 2048 entries
        const int row = i & 63;
        tmx_s[i] = __expf(tmx_s[i] - rmax_s[row]) * (1.f / rsum_s[row]);
    }
    __syncthreads();

    // ---- normalize the CTA's own p~ (L2-hot rewrite) ----
    {
        const int row = tid >> 2, quad = tid & 3;        // 4 threads per row
        const long grow = ((long)b * SEQ + q0 + row) * SEQ + quad * 1024;
#pragma unroll
        for (int t8 = 0; t8 < 8; t8++) {                  // 8 key-tiles per quad
            const float w = tmx_s[(quad * 8 + t8) * 64 + row];
            uint4* ptr = (uint4*)(g_p + grow + t8 * 128);
#pragma unroll
            for (int i = 0; i < 16; i++) {
                uint4 v = ptr[i];
                __half2* h = (__half2*)&v;
#pragma unroll
                for (int q = 0; q < 4; q++) {
                    float2 f = __half22float2(h[q]);
                    h[q] = __floats2half2_rn(f.x * w, f.y * w);
                }
                ptr[i] = v;
            }
        }
    }
}

// ---------------------------------------------------------------------------
// out = LayerNorm(A + B); optionally emit fp16 hi/lo split of out
// ---------------------------------------------------------------------------
__global__ __launch_bounds__(128) void add_ln_kernel(
    const float* __restrict__ A, const float* __restrict__ Bv,
    const float* __restrict__ g, const float* __restrict__ be,
    float* __restrict__ out, __half* __restrict__ ohi, __half* __restrict__ olo)
{
    const long row = blockIdx.x;
    const int tid = threadIdx.x;
    const int lane = tid & 31, wid = tid >> 5;
    __shared__ float red[4];

    float4 a = *(const float4*)(A + row * DM + tid * 4);
    float4 b = *(const float4*)(Bv + row * DM + tid * 4);
    float x0 = a.x + b.x, x1 = a.y + b.y, x2 = a.z + b.z, x3 = a.w + b.w;

    float s = x0 + x1 + x2 + x3;
#pragma unroll
    for (int o = 16; o > 0; o >>= 1) s += __shfl_xor_sync(0xFFFFFFFFu, s, o);
    if (lane == 0) red[wid] = s;
    __syncthreads();
    s = red[0] + red[1] + red[2] + red[3];
    const float mu = s * (1.0f / DM);
    __syncthreads();

    const float d0 = x0 - mu, d1 = x1 - mu, d2 = x2 - mu, d3 = x3 - mu;
    float vs = d0 * d0 + d1 * d1 + d2 * d2 + d3 * d3;
#pragma unroll
    for (int o = 16; o > 0; o >>= 1) vs += __shfl_xor_sync(0xFFFFFFFFu, vs, o);
    if (lane == 0) red[wid] = vs;
    __syncthreads();
    vs = red[0] + red[1] + red[2] + red[3];
    const float rs = rsqrtf(vs * (1.0f / DM) + 1e-5f);

    float4 gg = *(const float4*)(g + tid * 4);
    float4 bb = *(const float4*)(be + tid * 4);
    float o4[4];
    o4[0] = d0 * rs * gg.x + bb.x;
    o4[1] = d1 * rs * gg.y + bb.y;
    o4[2] = d2 * rs * gg.z + bb.z;
    o4[3] = d3 * rs * gg.w + bb.w;
    *(float4*)(out + row * DM + tid * 4) = *(float4*)o4;
    if (ohi) {
        __half hi[4], lo[4];
#pragma unroll
        for (int j = 0; j < 4; j++) {
            hi[j] = __float2half(o4[j]);
            lo[j] = __float2half(o4[j] - __half2float(hi[j]));
        }
        *(uint2*)(ohi + row * DM + tid * 4) = *(uint2*)hi;
        *(uint2*)(olo + row * DM + tid * 4) = *(uint2*)lo;
    }
}

// ---------------------------------------------------------------------------
// fp16 GEMM via mma.sync — BM=128, BN=128, 3-stage (Vt + FFN).
// mode 1: fp16 transposed (Vt)   mode 2: bias+leaky fp32
// ---------------------------------------------------------------------------
#define GM_STAGE 32768
#define GM_SMEM  (3 * GM_STAGE)      // 96 KB

__global__ __launch_bounds__(256) void gemm_mma(
    const __half* __restrict__ A0, const __half* __restrict__ A1,
    const __half* __restrict__ B0, const __half* __restrict__ B1,
    int npass, int Ktot,
    float* __restrict__ C, __half* __restrict__ Ct,
    const float* __restrict__ bias, int mode, int ldc)
{
    extern __shared__ char smem[];
    const uint32_t sb = smem_u32(smem);
    const int tid = threadIdx.x;
    const int lane = tid & 31, wid = tid >> 5;
    const int wr = wid >> 2, wc = wid & 3;
    const int m0 = blockIdx.y * 128, n0 = blockIdx.x * 128;

    const __half* Ap[2] = { A0, A1 };
    const __half* Bp[2] = { B0, B1 };

    const int kc = Ktot >> 6;
    const int nch = npass * kc;
    const int lrow = tid >> 3, lc = (tid & 7);

    auto load_chunk = [&](int c) {
        const int buf = c % 3;
        const int p = c / kc;
        const int k0 = (c - p * kc) << 6;
        const __half* A = Ap[p];
        const __half* B = Bp[p];
        const uint32_t sa = sb + buf * GM_STAGE;
        const uint32_t sbB = sa + 16384;
#pragma unroll
        for (int it = 0; it < 4; it++) {
            const int row = lrow + it * 32;
            cp16(sa + SW128(row * 128 + lc * 16), A + (long)(m0 + row) * Ktot + k0 + lc * 8);
            cp16(sbB + SW128(row * 128 + lc * 16), B + (long)(n0 + row) * Ktot + k0 + lc * 8);
        }
        CP_COMMIT();
    };

    float acc[4][4][4] = {};

    load_chunk(0);
    if (nch > 1) load_chunk(1);
    for (int c = 0; c < nch; c++) {
        if (c + 2 < nch) { load_chunk(c + 2); CP_WAIT(2); }
        else if (c + 1 < nch) { CP_WAIT(1); }
        else { CP_WAIT(0); }
        __syncthreads();

        const uint32_t sa = sb + (c % 3) * GM_STAGE;
        const uint32_t sbB = sa + 16384;
#pragma unroll
        for (int ks = 0; ks < 4; ks++) {
            uint32_t a[4][4];
#pragma unroll
            for (int mi = 0; mi < 4; mi++) {
                const int mr = wr * 64 + mi * 16 + (lane & 15);
                ldsm_x4(a[mi][0], a[mi][1], a[mi][2], a[mi][3],
                        sa + SW128(mr * 128 + ks * 32 + ((lane >> 4) << 4)));
            }
            uint32_t b[2][4];
#pragma unroll
            for (int j = 0; j < 2; j++) {
                const int nr = wc * 32 + j * 16 + (lane & 7) + ((lane >> 4) << 3);
                ldsm_x4(b[j][0], b[j][1], b[j][2], b[j][3],
                        sbB + SW128(nr * 128 + ks * 32 + (((lane >> 3) & 1) << 4)));
            }
#pragma unroll
            for (int mi = 0; mi < 4; mi++)
#pragma unroll
                for (int nj = 0; nj < 4; nj++)
                    mma16816(acc[mi][nj], a[mi],
                             b[nj >> 1][(nj & 1) * 2], b[nj >> 1][(nj & 1) * 2 + 1]);
        }
        __syncthreads();
    }

    const int crow = lane >> 2, ccol = (lane & 3) * 2;
    if (mode == 1) {
        __half* st = (__half*)smem;
#pragma unroll
        for (int mi = 0; mi < 4; mi++) {
#pragma unroll
            for (int nj = 0; nj < 4; nj++) {
                const int ml = wr * 64 + mi * 16 + crow;
                const int cl = wc * 32 + nj * 8 + ccol;
                st[(cl + 0) * 128 + ml]     = __float2half(acc[mi][nj][0]);
                st[(cl + 1) * 128 + ml]     = __float2half(acc[mi][nj][1]);
                st[(cl + 0) * 128 + ml + 8] = __float2half(acc[mi][nj][2]);
                st[(cl + 1) * 128 + ml + 8] = __float2half(acc[mi][nj][3]);
            }
        }
        __syncthreads();
        const long bb = m0 >> 12;
        const long s0 = m0 & 4095;
#pragma unroll
        for (int it = 0; it < 8; it++) {
            const int i = tid + it * 256;
            const int row = i >> 4, seg = i & 15;
            *(uint4*)(Ct + ((bb * DM) + n0 + row) * SEQ + s0 + seg * 8) =
                *(uint4*)(st + row * 128 + seg * 8);
        }
    } else {
#pragma unroll
        for (int mi = 0; mi < 4; mi++) {
#pragma unroll
            for (int nj = 0; nj < 4; nj++) {
                const long mr = m0 + wr * 64 + mi * 16 + crow;
                const int cl = n0 + wc * 32 + nj * 8 + ccol;
                const float b0 = bias[cl], b1 = bias[cl + 1];
                float v0 = acc[mi][nj][0] + b0, v1 = acc[mi][nj][1] + b1;
                float v2 = acc[mi][nj][2] + b0, v3 = acc[mi][nj][3] + b1;
                v0 = (v0 > 0.f) ? v0 : 0.01f * v0;
                v1 = (v1 > 0.f) ? v1 : 0.01f * v1;
                v2 = (v2 > 0.f) ? v2 : 0.01f * v2;
                v3 = (v3 > 0.f) ? v3 : 0.01f * v3;
                *(float2*)(C + mr * ldc + cl)       = make_float2(v0, v1);
                *(float2*)(C + (mr + 8) * ldc + cl) = make_float2(v2, v3);
            }
        }
    }
}

// ---------------------------------------------------------------------------
// PV GEMM: BM=128, BN=256, 2-stage cp.async. Halves P re-read traffic vs
// BN=128 (each P row-block read by 2 CTAs instead of 4) and doubles the
// MMA:ldsm ratio. Warp grid 2x4, warp tile 64x64. fp32 row-major output.
// ---------------------------------------------------------------------------
#define G2_STAGE 49152               // A 16KB + B 32KB
#define G2_SMEM  (2 * G2_STAGE)      // 96 KB -> 2 CTAs/SM

__global__ __launch_bounds__(256) void gemm_pv(
    const __half* __restrict__ P, const __half* __restrict__ Vt,
    float* __restrict__ H)
{
    extern __shared__ char smem[];
    const uint32_t sb = smem_u32(smem);
    const int tid = threadIdx.x;
    const int lane = tid & 31, wid = tid >> 5;
    const int wr = wid >> 2, wc = wid & 3;          // 2 x 4 warp grid
    const int m0 = blockIdx.y * 128, n0 = blockIdx.x * 256;
    const long zb = blockIdx.z;

    const __half* A = P + zb * (long)SEQ * SEQ;
    const __half* B = Vt + zb * (long)DM * SEQ;
    float* C = H + zb * (long)SEQ * DM;

    const int lrow = tid >> 3, lc = (tid & 7);
    const int nch = SEQ >> 6;                        // 64 chunks

    auto load_chunk = [&](int c) {
        const int k0 = c << 6;
        const uint32_t sa = sb + (c & 1) * G2_STAGE;
        const uint32_t sbB = sa + 16384;
#pragma unroll
        for (int it = 0; it < 4; it++) {             // A: 128 rows
            const int row = lrow + it * 32;
            cp16(sa + SW128(row * 128 + lc * 16), A + (long)(m0 + row) * SEQ + k0 + lc * 8);
        }
#pragma unroll
        for (int it = 0; it < 8; it++) {             // B: 256 rows
            const int row = lrow + it * 32;
            cp16(sbB + SW128(row * 128 + lc * 16), B + (long)(n0 + row) * SEQ + k0 + lc * 8);
        }
        CP_COMMIT();
    };

    float acc[4][8][4] = {};                          // 128 regs

    load_chunk(0);
    for (int c = 0; c < nch; c++) {
        if (c + 1 < nch) { load_chunk(c + 1); CP_WAIT(1); }
        else             { CP_WAIT(0); }
        __syncthreads();

        const uint32_t sa = sb + (c & 1) * G2_STAGE;
        const uint32_t sbB = sa + 16384;
#pragma unroll
        for (int ks = 0; ks < 4; ks++) {
            uint32_t a[4][4];
#pragma unroll
            for (int mi = 0; mi < 4; mi++) {
                const int mr = wr * 64 + mi * 16 + (lane & 15);
                ldsm_x4(a[mi][0], a[mi][1], a[mi][2], a[mi][3],
                        sa + SW128(mr * 128 + ks * 32 + ((lane >> 4) << 4)));
            }
            uint32_t bf[4][4];
#pragma unroll
            for (int j = 0; j < 4; j++) {
                const int nr = wc * 64 + j * 16 + (lane & 7) + ((lane >> 4) << 3);
                ldsm_x4(bf[j][0], bf[j][1], bf[j][2], bf[j][3],
                        sbB + SW128(nr * 128 + ks * 32 + (((lane >> 3) & 1) << 4)));
            }
#pragma unroll
            for (int mi = 0; mi < 4; mi++)
#pragma unroll
                for (int nj = 0; nj < 8; nj++)
                    mma16816(acc[mi][nj], a[mi],
                             bf[nj >> 1][(nj & 1) * 2], bf[nj >> 1][(nj & 1) * 2 + 1]);
        }
        __syncthreads();
    }

    const int crow = lane >> 2, ccol = (lane & 3) * 2;
#pragma unroll
    for (int mi = 0; mi < 4; mi++) {
#pragma unroll
        for (int nj = 0; nj < 8; nj++) {
            const long mr = m0 + wr * 64 + mi * 16 + crow;
            const int cl = n0 + wc * 64 + nj * 8 + ccol;
            *(float2*)(C + mr * DM + cl)       = make_float2(acc[mi][nj][0], acc[mi][nj][1]);
            *(float2*)(C + (mr + 8) * DM + cl) = make_float2(acc[mi][nj][2], acc[mi][nj][3]);
        }
    }
}

// ---------------------------------------------------------------------------
// Host launcher
// ---------------------------------------------------------------------------
extern "C" void kernel_launch(void* const* d_in, const int* in_sizes, int n_in,
                              void* d_out, int out_size)
{
    const float* x   = (const float*)d_in[0];
    const void*  am  = d_in[1];
    const void*  kpm = d_in[2];
    const float* Wq  = (const float*)d_in[3];
    const float* Wk  = (const float*)d_in[4];
    const float* Wv  = (const float*)d_in[5];
    const float* Wf  = (const float*)d_in[6];
    const float* bfp = (const float*)d_in[7];
    const float* g1  = (const float*)d_in[8];
    const float* b1  = (const float*)d_in[9];
    const float* g2  = (const float*)d_in[10];
    const float* b2  = (const float*)d_in[11];
    float* out = (float*)d_out;

    void *ph, *pz, *pp, *pxh, *pvt, *pzhi, *pzlo, *pwqk, *pwvt, *pwfhi, *pqk;
    cudaGetSymbolAddress(&pqk, g_qk);
    cudaGetSymbolAddress(&ph, g_h);
    cudaGetSymbolAddress(&pz, g_z);
    cudaGetSymbolAddress(&pp, g_p);
    cudaGetSymbolAddress(&pxh, g_xh);
    cudaGetSymbolAddress(&pvt, g_vt);
    cudaGetSymbolAddress(&pzhi, g_zhi);
    cudaGetSymbolAddress(&pzlo, g_zlo);
    cudaGetSymbolAddress(&pwqk, g_wqk);
    cudaGetSymbolAddress(&pwvt, g_wvt);
    cudaGetSymbolAddress(&pwfhi, g_wfhi);

    cudaFuncSetAttribute(gemm_mma, cudaFuncAttributeMaxDynamicSharedMemorySize, GM_SMEM);
    cudaFuncSetAttribute(gemm_pv, cudaFuncAttributeMaxDynamicSharedMemorySize, G2_SMEM);
    cudaFuncSetAttribute(attn_probs_kernel, cudaFuncAttributeMaxDynamicSharedMemorySize, AT_SMEM);

    // 0) mask detection + converts
    detect_mask_kernel<<<1, 32>>>(am);
    conv_x_h_kernel<<<(BS_ROWS * DM) / (256 * 4), 256>>>(x);
    concat_wqk_kernel<<<(DM * 32) / 256, 256>>>(Wq, Wk);
    wtrans_kernel<<<dim3(16, 16), dim3(32, 32)>>>(Wv, (__half*)pwvt);
    wtrans_kernel<<<dim3(16, 16), dim3(32, 32)>>>(Wf, (__half*)pwfhi);

    // 1) q|k projection (fp32, protects the sign(rowsum(q)) knife edge)
    gemm_f32<<<dim3(1, BS_ROWS / 64), 256>>>(x, (const float*)pwqk, (float*)pqk,
                                             BS_ROWS, 64, DM);
    rowstats_kernel<<<BS_ROWS / 256, 256>>>(kpm);

    // 2) Vt = (x @ Wv)^T fp16 (tensor cores, transposed store)
    gemm_mma<<<dim3(DM / 128, BS_ROWS / 128, 1), 256, GM_SMEM>>>(
        (const __half*)pxh, nullptr, (const __half*)pwvt, nullptr,
        1, DM, nullptr, (__half*)pvt, nullptr, 1, 0);

    // 3) SINGLE-PASS fused scores + mask + online softmax + L2-hot normalize
    attn_probs_kernel<<<dim3(SEQ / 64, BATCH), 256, AT_SMEM>>>(am);

    // 4) h = P @ V (BN=256 PV kernel: half the P re-reads, denser MMA stream)
    gemm_pv<<<dim3(DM / 256, SEQ / 128, BATCH), 256, G2_SMEM>>>(
        (const __half*)pp, (const __half*)pvt, (float*)ph);

    // 5) z = LN(x + h), emit fp16 hi/lo split
    add_ln_kernel<<<BS_ROWS, 128>>>(x, (const float*)ph, g1, b1, (float*)pz,
                                    (__half*)pzhi, (__half*)pzlo);

    // 6) y = leaky(z @ Wf + bf) via 2-pass split-fp16 (zhi + zlo vs Wf_hi)
    gemm_mma<<<dim3(DM / 128, BS_ROWS / 128, 1), 256, GM_SMEM>>>(
        (const __half*)pzhi, (const __half*)pzlo,
        (const __half*)pwfhi, (const __half*)pwfhi,
        2, DM, (float*)ph, nullptr, bfp, 2, DM);

    // 7) out = LN(z + y)
    add_ln_kernel<<<BS_ROWS, 128>>>((const float*)pz, (const float*)ph, g2, b2, out,
                                    nullptr, nullptr);
}

// round 16
// speedup vs baseline: 1.3220x; 1.0613x over previous
#include <cuda_runtime.h>
#include <cuda_fp16.h>
#include <cstdint>
#include <cfloat>

// ---------------------------------------------------------------------------
// Problem constants
// ---------------------------------------------------------------------------
#define BATCH 4
#define SEQ   4096
#define DM    512
#define DK    32
#define BS_ROWS (BATCH * SEQ)           // 16384
static const float INV_DK = 0.17677669529663687f;   // 1/sqrt(32)
#define NINF_F (-1e24f)

// ---------------------------------------------------------------------------
// Scratch (static device globals; allocations are forbidden)
// ---------------------------------------------------------------------------
static __device__ int      g_mask_mode;
static __device__ float    g_qk[BS_ROWS * 64];                   // q | k
static __device__ float    g_crow[BS_ROWS];
static __device__ float    g_padf[BS_ROWS];
static __device__ float    g_tm[(size_t)BATCH * 32 * SEQ];       // [b][kt][row] tile max
static __device__ float    g_mfin[BS_ROWS];
static __device__ float    g_isum[BS_ROWS];
static __device__ float    g_h[(size_t)BS_ROWS * DM];            // 32 MB
static __device__ float    g_z[(size_t)BS_ROWS * DM];            // 32 MB
static __device__ __half   g_p[(size_t)BATCH * SEQ * SEQ];       // 128 MB p~ (unnormalized)
static __device__ __half   g_xh[(size_t)BS_ROWS * DM];           // x fp16
static __device__ __half   g_vt[(size_t)BATCH * DM * SEQ];       // V^T fp16
static __device__ __half   g_zhi[(size_t)BS_ROWS * DM];
static __device__ __half   g_zlo[(size_t)BS_ROWS * DM];
static __device__ float    g_wqk[DM * 64];                       // Wq|Wk fp32
static __device__ __half   g_wvt[DM * DM];
static __device__ __half   g_wfhi[DM * DM];

// ---------------------------------------------------------------------------
// PTX helpers (generic compute_103 safe)
// ---------------------------------------------------------------------------
__device__ __forceinline__ uint32_t smem_u32(const void* p) {
    uint32_t a;
    asm("{ .reg .u64 t; cvta.to.shared.u64 t, %1; cvt.u32.u64 %0, t; }" : "=r"(a) : "l"(p));
    return a;
}
__device__ __forceinline__ void cp16(uint32_t dst, const void* src) {
    asm volatile("cp.async.cg.shared.global [%0], [%1], 16;" :: "r"(dst), "l"(src));
}
#define CP_COMMIT()  asm volatile("cp.async.commit_group;" ::: "memory")
#define CP_WAIT(n)   asm volatile("cp.async.wait_group %0;" :: "n"(n) : "memory")

__device__ __forceinline__ void ldsm_x4(uint32_t& r0, uint32_t& r1, uint32_t& r2,
                                        uint32_t& r3, uint32_t addr) {
    asm volatile("ldmatrix.sync.aligned.m8n8.x4.shared.b16 {%0,%1,%2,%3}, [%4];"
                 : "=r"(r0), "=r"(r1), "=r"(r2), "=r"(r3) : "r"(addr));
}
__device__ __forceinline__ void mma16816(float* c, const uint32_t* a,
                                         uint32_t b0, uint32_t b1) {
    asm volatile(
        "mma.sync.aligned.m16n8k16.row.col.f32.f16.f16.f32 "
        "{%0,%1,%2,%3}, {%4,%5,%6,%7}, {%8,%9}, {%0,%1,%2,%3};"
        : "+f"(c[0]), "+f"(c[1]), "+f"(c[2]), "+f"(c[3])
        : "r"(a[0]), "r"(a[1]), "r"(a[2]), "r"(a[3]), "r"(b0), "r"(b1));
}
__device__ __forceinline__ uint32_t cvt_tf32(float v) {
    uint32_t r;
    asm("cvt.rna.tf32.f32 %0, %1;" : "=r"(r) : "f"(v));
    return r;
}
__device__ __forceinline__ void mma_tf32(float* c, const uint32_t* a,
                                         uint32_t b0, uint32_t b1) {
    asm volatile(
        "mma.sync.aligned.m16n8k8.row.col.f32.tf32.tf32.f32 "
        "{%0,%1,%2,%3}, {%4,%5,%6,%7}, {%8,%9}, {%0,%1,%2,%3};"
        : "+f"(c[0]), "+f"(c[1]), "+f"(c[2]), "+f"(c[3])
        : "r"(a[0]), "r"(a[1]), "r"(a[2]), "r"(a[3]), "r"(b0), "r"(b1));
}
#define SW128(off) ((off) ^ (((off) >> 3) & 0x70))

// ---------------------------------------------------------------------------
// Mask dtype handling
// ---------------------------------------------------------------------------
__device__ __forceinline__ bool mask_true(const void* p, long i, int mode)
{
    if (mode == 0) return ((const float*)p)[i] != 0.0f;
    if (mode == 1) return ((const int*)p)[i] != 0;
    if (mode == 2) return ((const unsigned short*)p)[i] != 0;
    return ((const unsigned char*)p)[i] != 0;
}

__global__ void detect_mask_kernel(const void* __restrict__ am)
{
    if (threadIdx.x != 0 || blockIdx.x != 0) return;
    const unsigned int* w = (const unsigned int*)am;
    bool f32ok = true, i32ok = true, bf16ok = true;
    for (int i = 0; i < 1024; i++) {
        unsigned int v = w[i];
        if (!(v == 0u || v == 0x3F800000u)) f32ok = false;
        if (!(v == 0u || v == 1u)) i32ok = false;
        unsigned int h0 = v & 0xFFFFu, h1 = v >> 16;
        if (!((h0 == 0u || h0 == 0x3F80u) && (h1 == 0u || h1 == 0x3F80u))) bf16ok = false;
    }
    g_mask_mode = f32ok ? 0 : (i32ok ? 1 : (bf16ok ? 2 : 3));
}

// ---------------------------------------------------------------------------
// fp32 GEMM (q|k projection, N=64)
// ---------------------------------------------------------------------------
__global__ __launch_bounds__(256) void gemm_f32(
    const float* __restrict__ A, const float* __restrict__ B, float* __restrict__ C,
    int M, int N, int K)
{
    __shared__ float As[16][64];
    __shared__ float Bs[16][64];
    const int tid = threadIdx.x;
    const int m0 = blockIdx.y * 64, n0 = blockIdx.x * 64;
    const int tx = tid & 15, ty = tid >> 4;
    const int arow = tid >> 2, ac = (tid & 3) * 4;
    const int brow = tid >> 4, bc = (tid & 15) * 4;

    float acc[4][4] = {};
    for (int k0 = 0; k0 < K; k0 += 16) {
        float4 av = *(const float4*)(A + (long)(m0 + arow) * K + k0 + ac);
        As[ac + 0][arow] = av.x; As[ac + 1][arow] = av.y;
        As[ac + 2][arow] = av.z; As[ac + 3][arow] = av.w;
        float4 bv = *(const float4*)(B + (long)(k0 + brow) * N + n0 + bc);
        *(float4*)&Bs[brow][bc] = bv;
        __syncthreads();
#pragma unroll
        for (int kk = 0; kk < 16; kk++) {
            float4 a = *(const float4*)&As[kk][ty * 4];
            float4 b = *(const float4*)&Bs[kk][tx * 4];
            acc[0][0] += a.x * b.x; acc[0][1] += a.x * b.y; acc[0][2] += a.x * b.z; acc[0][3] += a.x * b.w;
            acc[1][0] += a.y * b.x; acc[1][1] += a.y * b.y; acc[1][2] += a.y * b.z; acc[1][3] += a.y * b.w;
            acc[2][0] += a.z * b.x; acc[2][1] += a.z * b.y; acc[2][2] += a.z * b.z; acc[2][3] += a.z * b.w;
            acc[3][0] += a.w * b.x; acc[3][1] += a.w * b.y; acc[3][2] += a.w * b.z; acc[3][3] += a.w * b.w;
        }
        __syncthreads();
    }
#pragma unroll
    for (int i = 0; i < 4; i++) {
        const int m = m0 + ty * 4 + i;
#pragma unroll
        for (int j = 0; j < 4; j++)
            C[(long)m * N + n0 + tx * 4 + j] = acc[i][j];
    }
}

// ---------------------------------------------------------------------------
// Converts
// ---------------------------------------------------------------------------
__global__ void conv_x_h_kernel(const float* __restrict__ x)
{
    const long i = ((long)blockIdx.x * blockDim.x + threadIdx.x) * 4;
    float4 v = *(const float4*)(x + i);
    __half o[4] = { __float2half(v.x), __float2half(v.y),
                    __float2half(v.z), __float2half(v.w) };
    *(uint2*)(g_xh + i) = *(uint2*)o;
}

__global__ void concat_wqk_kernel(const float* __restrict__ Wq, const float* __restrict__ Wk)
{
    const int idx = blockIdx.x * blockDim.x + threadIdx.x;
    const int k = idx >> 5, j = idx & 31;
    g_wqk[k * 64 + j]      = Wq[k * 32 + j];
    g_wqk[k * 64 + 32 + j] = Wk[k * 32 + j];
}

__global__ void wtrans_kernel(const float* __restrict__ W, __half* __restrict__ Thi)
{
    __shared__ float tile[32][33];
    const int k0 = blockIdx.y * 32, n0 = blockIdx.x * 32;
    tile[threadIdx.y][threadIdx.x] = W[(long)(k0 + threadIdx.y) * DM + n0 + threadIdx.x];
    __syncthreads();
    const float v = tile[threadIdx.x][threadIdx.y];
    Thi[(long)(n0 + threadIdx.y) * DM + k0 + threadIdx.x] = __float2half(v);
}

// ---------------------------------------------------------------------------
// rowstats: c_i = rowsum(q) * (-1e24) * inv_dk ; pad flag
// ---------------------------------------------------------------------------
__global__ void rowstats_kernel(const void* __restrict__ pad)
{
    const int row = blockIdx.x * blockDim.x + threadIdx.x;
    if (row >= BS_ROWS) return;
    float s = 0.f;
#pragma unroll
    for (int d = 0; d < DK; d++) s += g_qk[row * 64 + d];
    g_crow[row] = s * NINF_F * INV_DK;
    g_padf[row] = mask_true(pad, row, g_mask_mode) ? 1.f : 0.f;
}

// ---------------------------------------------------------------------------
// SINGLE-PASS fused attention: scores (tf32) + exact masking + online softmax.
// Writes UNNORMALIZED p~ = exp(s - m_kt) fp16, plus g_tm[b][kt][row] = m_kt
// (running max) and g_mfin / g_isum. The PV GEMM folds the normalization
// p = p~ * exp(m_kt - m_fin)/sum into its A fragments (fp16 table).
// NO tail rewrite — saves ~256 MB of L2 round trip vs round 10/15.
// ---------------------------------------------------------------------------
#define AT_OFF_Q    0          // 64*36*4  = 9216
#define AT_OFF_K    9216       // 2*128*144 = 36864
#define AT_OFF_BITS 46080      // 64*4*4 = 1024 (current tile only)
#define AT_OFF_PAD  47104      // 128*4 = 512
#define AT_OFF_CROW 47616      // 64*4
#define AT_OFF_RMAX 47872
#define AT_OFF_RSUM 48128
#define AT_OFF_PMAX 48384      // 128*4
#define AT_OFF_PSUM 48896      // 128*4
#define AT_SMEM     49408

__global__ __launch_bounds__(256) void attn_probs_kernel(const void* __restrict__ am)
{
    extern __shared__ char dsm[];
    float*    Qs     = (float*)(dsm + AT_OFF_Q);
    float*    KsBase = (float*)(dsm + AT_OFF_K);
    uint32_t* bitsA  = (uint32_t*)(dsm + AT_OFF_BITS);
    uint32_t* padb   = (uint32_t*)(dsm + AT_OFF_PAD);
    float*    crow_s = (float*)(dsm + AT_OFF_CROW);
    float*    rmax_s = (float*)(dsm + AT_OFF_RMAX);
    float*    rsum_s = (float*)(dsm + AT_OFF_RSUM);
    float*    pmax_s = (float*)(dsm + AT_OFF_PMAX);
    float*    psum_s = (float*)(dsm + AT_OFF_PSUM);
    const uint32_t sb = smem_u32(dsm);

    const int tid = threadIdx.x;
    const int lane = tid & 31, wid = tid >> 5;
    const int wr = wid >> 1, wk = wid & 1;
    const int b = blockIdx.y;
    const int q0 = blockIdx.x * 64;
    const int mode = g_mask_mode;

    // ---- init ----
#pragma unroll
    for (int it = 0; it < 2; it++) {
        const int i = tid + it * 256;
        const int row = i >> 3, c4 = i & 7;
        *(float4*)(Qs + row * 36 + c4 * 4) =
            *(const float4*)(g_qk + ((long)b * SEQ + q0 + row) * 64 + c4 * 4);
    }
#pragma unroll
    for (int it = 0; it < 16; it++) {
        const int idx = tid + it * 256;
        const bool t = g_padf[(long)b * SEQ + idx] != 0.f;
        const uint32_t bal = __ballot_sync(0xFFFFFFFFu, t);
        if (lane == 0) padb[idx >> 5] = bal;
    }
    if (tid < 64) {
        crow_s[tid] = g_crow[(long)b * SEQ + q0 + tid];
        rmax_s[tid] = -FLT_MAX;
        rsum_s[tid] = 0.f;
    }
    __syncthreads();

    auto load_k = [&](int kt) {
        const int buf = kt & 1;
        const float* src = g_qk + ((long)b * SEQ + kt * 128) * 64 + 32;
        const uint32_t dstb = sb + AT_OFF_K + buf * 18432;
#pragma unroll
        for (int it = 0; it < 4; it++) {
            const int i = tid + it * 256;
            const int row = i >> 3, seg = i & 7;
            cp16(dstb + row * 144 + seg * 16, src + row * 64 + seg * 4);
        }
        CP_COMMIT();
    };

    load_k(0);
    for (int kt = 0; kt < 32; kt++) {
        if (kt + 1 < 32) load_k(kt + 1);

        // attn_mask bits for THIS tile: warp w owns rows w*8..w*8+7
        {
            const long rbase = ((long)b * SEQ + q0 + wid * 8) * SEQ + kt * 128;
#pragma unroll
            for (int rr = 0; rr < 8; rr++) {
#pragma unroll
                for (int cw = 0; cw < 4; cw++) {
                    const bool t = mask_true(am, rbase + (long)rr * SEQ + cw * 32 + lane, mode);
                    const uint32_t bal = __ballot_sync(0xFFFFFFFFu, t);
                    if (lane == 0) bitsA[(wid * 8 + rr) * 4 + cw] = bal;
                }
            }
        }
        if (kt + 1 < 32) { CP_WAIT(1); } else { CP_WAIT(0); }
        __syncthreads();

        // ---- score tile (tf32) + exact masking ----
        float s[8][4];
        {
            const float* Kst = KsBase + (kt & 1) * 4608;
#pragma unroll
            for (int nj = 0; nj < 8; nj++) { s[nj][0] = s[nj][1] = s[nj][2] = s[nj][3] = 0.f; }
#pragma unroll
            for (int ks = 0; ks < 4; ks++) {
                const int kb = ks * 8 + (lane & 3);
                uint32_t A[4];
                const int r = wr * 16 + (lane >> 2);
                A[0] = cvt_tf32(Qs[r * 36 + kb]);
                A[1] = cvt_tf32(Qs[(r + 8) * 36 + kb]);
                A[2] = cvt_tf32(Qs[r * 36 + kb + 4]);
                A[3] = cvt_tf32(Qs[(r + 8) * 36 + kb + 4]);
#pragma unroll
                for (int nj = 0; nj < 8; nj++) {
                    const int n = wk * 64 + nj * 8 + (lane >> 2);
                    const uint32_t B0 = cvt_tf32(Kst[n * 36 + kb]);
                    const uint32_t B1 = cvt_tf32(Kst[n * 36 + kb + 4]);
                    mma_tf32(s[nj], A, B0, B1);
                }
            }
            const int r0 = wr * 16 + (lane >> 2), r1 = r0 + 8;
            const float cr0 = crow_s[r0], cr1 = crow_s[r1];
#pragma unroll
            for (int nj = 0; nj < 8; nj++) {
                const int kloc = wk * 64 + nj * 8 + (lane & 3) * 2;     // even
                const uint32_t pw = padb[(kt * 128 + kloc) >> 5];
                const uint32_t w0 = bitsA[r0 * 4 + (kloc >> 5)];
                const uint32_t w1 = bitsA[r1 * 4 + (kloc >> 5)];
                const int sh = kloc & 31;
                float v0 = s[nj][0] * INV_DK, v1 = s[nj][1] * INV_DK;
                float v2 = s[nj][2] * INV_DK, v3 = s[nj][3] * INV_DK;
                if ((pw >> sh) & 1)       { v0 = cr0; v2 = cr1; }
                if ((pw >> (sh + 1)) & 1) { v1 = cr0; v3 = cr1; }
                if ((w0 >> sh) & 1)       v0 = NINF_F;
                if ((w0 >> (sh + 1)) & 1) v1 = NINF_F;
                if ((w1 >> sh) & 1)       v2 = NINF_F;
                if ((w1 >> (sh + 1)) & 1) v3 = NINF_F;
                s[nj][0] = v0; s[nj][1] = v1; s[nj][2] = v2; s[nj][3] = v3;
            }
        }

        // ---- tile max ----
        const int r0 = wr * 16 + (lane >> 2), r1 = r0 + 8;
        float mx0 = -FLT_MAX, mx1 = -FLT_MAX;
#pragma unroll
        for (int nj = 0; nj < 8; nj++) {
            mx0 = fmaxf(mx0, fmaxf(s[nj][0], s[nj][1]));
            mx1 = fmaxf(mx1, fmaxf(s[nj][2], s[nj][3]));
        }
        mx0 = fmaxf(mx0, __shfl_xor_sync(0xFFFFFFFFu, mx0, 1));
        mx0 = fmaxf(mx0, __shfl_xor_sync(0xFFFFFFFFu, mx0, 2));
        mx1 = fmaxf(mx1, __shfl_xor_sync(0xFFFFFFFFu, mx1, 1));
        mx1 = fmaxf(mx1, __shfl_xor_sync(0xFFFFFFFFu, mx1, 2));
        if ((lane & 3) == 0) { pmax_s[r0 * 2 + wk] = mx0; pmax_s[r1 * 2 + wk] = mx1; }
        __syncthreads();

        // ---- combine running stats; record m_kt to global (coalesced) ----
        if (tid < 64) {
            const float tm = fmaxf(pmax_s[2 * tid], pmax_s[2 * tid + 1]);
            const float mo = rmax_s[tid];
            const float mn = fmaxf(mo, tm);
            rsum_s[tid] *= __expf(mo - mn);
            rmax_s[tid] = mn;
            pmax_s[2 * tid] = mn;
            g_tm[((long)b * 32 + kt) * SEQ + q0 + tid] = mn;
        }
        __syncthreads();

        // ---- p~ = exp(s - m_kt): accumulate sum AND store fp16 ----
        const float mn0 = pmax_s[2 * r0], mn1 = pmax_s[2 * r1];
        const long gr0 = ((long)b * SEQ + q0 + r0) * SEQ;
        const long gr1 = ((long)b * SEQ + q0 + r1) * SEQ;
        float sm0 = 0.f, sm1 = 0.f;
#pragma unroll
        for (int nj = 0; nj < 8; nj++) {
            const int kk = kt * 128 + wk * 64 + nj * 8 + (lane & 3) * 2;
            const float e0 = __expf(s[nj][0] - mn0), e1 = __expf(s[nj][1] - mn0);
            const float e2 = __expf(s[nj][2] - mn1), e3 = __expf(s[nj][3] - mn1);
            sm0 += e0 + e1;
            sm1 += e2 + e3;
            *(__half2*)(g_p + gr0 + kk) = __floats2half2_rn(e0, e1);
            *(__half2*)(g_p + gr1 + kk) = __floats2half2_rn(e2, e3);
        }
        sm0 += __shfl_xor_sync(0xFFFFFFFFu, sm0, 1);
        sm0 += __shfl_xor_sync(0xFFFFFFFFu, sm0, 2);
        sm1 += __shfl_xor_sync(0xFFFFFFFFu, sm1, 1);
        sm1 += __shfl_xor_sync(0xFFFFFFFFu, sm1, 2);
        if ((lane & 3) == 0) { psum_s[r0 * 2 + wk] = sm0; psum_s[r1 * 2 + wk] = sm1; }
        __syncthreads();
        if (tid < 64) rsum_s[tid] += psum_s[2 * tid] + psum_s[2 * tid + 1];
        __syncthreads();
    }

    if (tid < 64) {
        g_mfin[(long)b * SEQ + q0 + tid] = rmax_s[tid];
        g_isum[(long)b * SEQ + q0 + tid] = 1.f / rsum_s[tid];
    }
}

// ---------------------------------------------------------------------------
// out = LayerNorm(A + B); optionally emit fp16 hi/lo split of out
// ---------------------------------------------------------------------------
__global__ __launch_bounds__(128) void add_ln_kernel(
    const float* __restrict__ A, const float* __restrict__ Bv,
    const float* __restrict__ g, const float* __restrict__ be,
    float* __restrict__ out, __half* __restrict__ ohi, __half* __restrict__ olo)
{
    const long row = blockIdx.x;
    const int tid = threadIdx.x;
    const int lane = tid & 31, wid = tid >> 5;
    __shared__ float red[4];

    float4 a = *(const float4*)(A + row * DM + tid * 4);
    float4 b = *(const float4*)(Bv + row * DM + tid * 4);
    float x0 = a.x + b.x, x1 = a.y + b.y, x2 = a.z + b.z, x3 = a.w + b.w;

    float s = x0 + x1 + x2 + x3;
#pragma unroll
    for (int o = 16; o > 0; o >>= 1) s += __shfl_xor_sync(0xFFFFFFFFu, s, o);
    if (lane == 0) red[wid] = s;
    __syncthreads();
    s = red[0] + red[1] + red[2] + red[3];
    const float mu = s * (1.0f / DM);
    __syncthreads();

    const float d0 = x0 - mu, d1 = x1 - mu, d2 = x2 - mu, d3 = x3 - mu;
    float vs = d0 * d0 + d1 * d1 + d2 * d2 + d3 * d3;
#pragma unroll
    for (int o = 16; o > 0; o >>= 1) vs += __shfl_xor_sync(0xFFFFFFFFu, vs, o);
    if (lane == 0) red[wid] = vs;
    __syncthreads();
    vs = red[0] + red[1] + red[2] + red[3];
    const float rs = rsqrtf(vs * (1.0f / DM) + 1e-5f);

    float4 gg = *(const float4*)(g + tid * 4);
    float4 bb = *(const float4*)(be + tid * 4);
    float o4[4];
    o4[0] = d0 * rs * gg.x + bb.x;
    o4[1] = d1 * rs * gg.y + bb.y;
    o4[2] = d2 * rs * gg.z + bb.z;
    o4[3] = d3 * rs * gg.w + bb.w;
    *(float4*)(out + row * DM + tid * 4) = *(float4*)o4;
    if (ohi) {
        __half hi[4], lo[4];
#pragma unroll
        for (int j = 0; j < 4; j++) {
            hi[j] = __float2half(o4[j]);
            lo[j] = __float2half(o4[j] - __half2float(hi[j]));
        }
        *(uint2*)(ohi + row * DM + tid * 4) = *(uint2*)hi;
        *(uint2*)(olo + row * DM + tid * 4) = *(uint2*)lo;
    }
}

// ---------------------------------------------------------------------------
// fp16 GEMM via mma.sync — BM=128, BN=128, 3-stage (Vt + FFN).
// mode 1: fp16 transposed (Vt)   mode 2: bias+leaky fp32
// ---------------------------------------------------------------------------
#define GM_STAGE 32768
#define GM_SMEM  (3 * GM_STAGE)      // 96 KB

__global__ __launch_bounds__(256) void gemm_mma(
    const __half* __restrict__ A0, const __half* __restrict__ A1,
    const __half* __restrict__ B0, const __half* __restrict__ B1,
    int npass, int Ktot,
    float* __restrict__ C, __half* __restrict__ Ct,
    const float* __restrict__ bias, int mode, int ldc)
{
    extern __shared__ char smem[];
    const uint32_t sb = smem_u32(smem);
    const int tid = threadIdx.x;
    const int lane = tid & 31, wid = tid >> 5;
    const int wr = wid >> 2, wc = wid & 3;
    const int m0 = blockIdx.y * 128, n0 = blockIdx.x * 128;

    const __half* Ap[2] = { A0, A1 };
    const __half* Bp[2] = { B0, B1 };

    const int kc = Ktot >> 6;
    const int nch = npass * kc;
    const int lrow = tid >> 3, lc = (tid & 7);

    auto load_chunk = [&](int c) {
        const int buf = c % 3;
        const int p = c / kc;
        const int k0 = (c - p * kc) << 6;
        const __half* A = Ap[p];
        const __half* B = Bp[p];
        const uint32_t sa = sb + buf * GM_STAGE;
        const uint32_t sbB = sa + 16384;
#pragma unroll
        for (int it = 0; it < 4; it++) {
            const int row = lrow + it * 32;
            cp16(sa + SW128(row * 128 + lc * 16), A + (long)(m0 + row) * Ktot + k0 + lc * 8);
            cp16(sbB + SW128(row * 128 + lc * 16), B + (long)(n0 + row) * Ktot + k0 + lc * 8);
        }
        CP_COMMIT();
    };

    float acc[4][4][4] = {};

    load_chunk(0);
    if (nch > 1) load_chunk(1);
    for (int c = 0; c < nch; c++) {
        if (c + 2 < nch) { load_chunk(c + 2); CP_WAIT(2); }
        else if (c + 1 < nch) { CP_WAIT(1); }
        else { CP_WAIT(0); }
        __syncthreads();

        const uint32_t sa = sb + (c % 3) * GM_STAGE;
        const uint32_t sbB = sa + 16384;
#pragma unroll
        for (int ks = 0; ks < 4; ks++) {
            uint32_t a[4][4];
#pragma unroll
            for (int mi = 0; mi < 4; mi++) {
                const int mr = wr * 64 + mi * 16 + (lane & 15);
                ldsm_x4(a[mi][0], a[mi][1], a[mi][2], a[mi][3],
                        sa + SW128(mr * 128 + ks * 32 + ((lane >> 4) << 4)));
            }
            uint32_t b[2][4];
#pragma unroll
            for (int j = 0; j < 2; j++) {
                const int nr = wc * 32 + j * 16 + (lane & 7) + ((lane >> 4) << 3);
                ldsm_x4(b[j][0], b[j][1], b[j][2], b[j][3],
                        sbB + SW128(nr * 128 + ks * 32 + (((lane >> 3) & 1) << 4)));
            }
#pragma unroll
            for (int mi = 0; mi < 4; mi++)
#pragma unroll
                for (int nj = 0; nj < 4; nj++)
                    mma16816(acc[mi][nj], a[mi],
                             b[nj >> 1][(nj & 1) * 2], b[nj >> 1][(nj & 1) * 2 + 1]);
        }
        __syncthreads();
    }

    const int crow = lane >> 2, ccol = (lane & 3) * 2;
    if (mode == 1) {
        __half* st = (__half*)smem;
#pragma unroll
        for (int mi = 0; mi < 4; mi++) {
#pragma unroll
            for (int nj = 0; nj < 4; nj++) {
                const int ml = wr * 64 + mi * 16 + crow;
                const int cl = wc * 32 + nj * 8 + ccol;
                st[(cl + 0) * 128 + ml]     = __float2half(acc[mi][nj][0]);
                st[(cl + 1) * 128 + ml]     = __float2half(acc[mi][nj][1]);
                st[(cl + 0) * 128 + ml + 8] = __float2half(acc[mi][nj][2]);
                st[(cl + 1) * 128 + ml + 8] = __float2half(acc[mi][nj][3]);
            }
        }
        __syncthreads();
        const long bb = m0 >> 12;
        const long s0 = m0 & 4095;
#pragma unroll
        for (int it = 0; it < 8; it++) {
            const int i = tid + it * 256;
            const int row = i >> 4, seg = i & 15;
            *(uint4*)(Ct + ((bb * DM) + n0 + row) * SEQ + s0 + seg * 8) =
                *(uint4*)(st + row * 128 + seg * 8);
        }
    } else {
#pragma unroll
        for (int mi = 0; mi < 4; mi++) {
#pragma unroll
            for (int nj = 0; nj < 4; nj++) {
                const long mr = m0 + wr * 64 + mi * 16 + crow;
                const int cl = n0 + wc * 32 + nj * 8 + ccol;
                const float b0 = bias[cl], b1 = bias[cl + 1];
                float v0 = acc[mi][nj][0] + b0, v1 = acc[mi][nj][1] + b1;
                float v2 = acc[mi][nj][2] + b0, v3 = acc[mi][nj][3] + b1;
                v0 = (v0 > 0.f) ? v0 : 0.01f * v0;
                v1 = (v1 > 0.f) ? v1 : 0.01f * v1;
                v2 = (v2 > 0.f) ? v2 : 0.01f * v2;
                v3 = (v3 > 0.f) ? v3 : 0.01f * v3;
                *(float2*)(C + mr * ldc + cl)       = make_float2(v0, v1);
                *(float2*)(C + (mr + 8) * ldc + cl) = make_float2(v2, v3);
            }
        }
    }
}

// ---------------------------------------------------------------------------
// PV GEMM: BM=128, BN=256, 2-stage cp.async, with folded normalization.
// A fragments scaled by scH[kt][row] = fp16(exp(m_kt - m_fin)/sum) — the
// kt-major fp16 layout makes the warp's 8 distinct row reads consecutive
// (broadcast across 4 lanes, <=2-way U16 conflict) unlike round 9's
// stride-32-float 8-way conflict. Warp grid 2x4, warp tile 64x64.
// ---------------------------------------------------------------------------
#define G2_STAGE 49152               // A 16KB + B 32KB
#define G2_TBL   (2 * G2_STAGE)      // 98304
#define G2_SMEM  (G2_TBL + 32 * 128 * 2)   // + 8 KB fp16 scale table

__global__ __launch_bounds__(256) void gemm_pv(
    const __half* __restrict__ P, const __half* __restrict__ Vt,
    float* __restrict__ H,
    const float* __restrict__ tm, const float* __restrict__ mfin,
    const float* __restrict__ isum)
{
    extern __shared__ char smem[];
    const uint32_t sb = smem_u32(smem);
    __half* scH = (__half*)(smem + G2_TBL);
    const uint32_t scb = sb + G2_TBL;
    const int tid = threadIdx.x;
    const int lane = tid & 31, wid = tid >> 5;
    const int wr = wid >> 2, wc = wid & 3;          // 2 x 4 warp grid
    const int m0 = blockIdx.y * 128, n0 = blockIdx.x * 256;
    const long zb = blockIdx.z;

    const __half* A = P + zb * (long)SEQ * SEQ;
    const __half* B = Vt + zb * (long)DM * SEQ;
    float* C = H + zb * (long)SEQ * DM;

    const int lrow = tid >> 3, lc = (tid & 7);
    const int nch = SEQ >> 6;                        // 64 chunks

    auto load_chunk = [&](int c) {
        const int k0 = c << 6;
        const uint32_t sa = sb + (c & 1) * G2_STAGE;
        const uint32_t sbB = sa + 16384;
#pragma unroll
        for (int it = 0; it < 4; it++) {             // A: 128 rows
            const int row = lrow + it * 32;
            cp16(sa + SW128(row * 128 + lc * 16), A + (long)(m0 + row) * SEQ + k0 + lc * 8);
        }
#pragma unroll
        for (int it = 0; it < 8; it++) {             // B: 256 rows
            const int row = lrow + it * 32;
            cp16(sbB + SW128(row * 128 + lc * 16), B + (long)(n0 + row) * SEQ + k0 + lc * 8);
        }
        CP_COMMIT();
    };

    float acc[4][8][4] = {};                          // 128 regs

    load_chunk(0);
    // build the fp16 normalization table while the first loads fly
    for (int i = tid; i < 32 * 128; i += 256) {
        const int kt = i >> 7, row = i & 127;
        const long gr = zb * (long)SEQ + m0 + row;
        scH[i] = __float2half(__expf(tm[(zb * 32 + kt) * (long)SEQ + m0 + row] - mfin[gr])
                              * isum[gr]);
    }

    for (int c = 0; c < nch; c++) {
        if (c + 1 < nch) { load_chunk(c + 1); CP_WAIT(1); }
        else             { CP_WAIT(0); }
        __syncthreads();

        const uint32_t sa = sb + (c & 1) * G2_STAGE;
        const uint32_t sbB = sa + 16384;
        const int ktc = c >> 1;                      // 128-key tile index
#pragma unroll
        for (int ks = 0; ks < 4; ks++) {
            uint32_t a[4][4];
#pragma unroll
            for (int mi = 0; mi < 4; mi++) {
                const int mr = wr * 64 + mi * 16 + (lane & 15);
                ldsm_x4(a[mi][0], a[mi][1], a[mi][2], a[mi][3],
                        sa + SW128(mr * 128 + ks * 32 + ((lane >> 4) << 4)));
            }
            // fold normalization into A fragments (conflict-free fp16 table)
#pragma unroll
            for (int mi = 0; mi < 4; mi++) {
                const int rb = wr * 64 + mi * 16 + (lane >> 2);
                __half s0h, s1h;
                asm volatile("ld.shared.u16 %0, [%1];"
                             : "=h"(*(unsigned short*)&s0h)
                             : "r"(scb + (uint32_t)(ktc * 128 + rb) * 2));
                asm volatile("ld.shared.u16 %0, [%1];"
                             : "=h"(*(unsigned short*)&s1h)
                             : "r"(scb + (uint32_t)(ktc * 128 + rb + 8) * 2));
                const __half2 h0 = __half2half2(s0h);
                const __half2 h1 = __half2half2(s1h);
                __half2* av = (__half2*)a[mi];
                av[0] = __hmul2(av[0], h0);
                av[1] = __hmul2(av[1], h1);
                av[2] = __hmul2(av[2], h0);
                av[3] = __hmul2(av[3], h1);
            }
            uint32_t bf[4][4];
#pragma unroll
            for (int j = 0; j < 4; j++) {
                const int nr = wc * 64 + j * 16 + (lane & 7) + ((lane >> 4) << 3);
                ldsm_x4(bf[j][0], bf[j][1], bf[j][2], bf[j][3],
                        sbB + SW128(nr * 128 + ks * 32 + (((lane >> 3) & 1) << 4)));
            }
#pragma unroll
            for (int mi = 0; mi < 4; mi++)
#pragma unroll
                for (int nj = 0; nj < 8; nj++)
                    mma16816(acc[mi][nj], a[mi],
                             bf[nj >> 1][(nj & 1) * 2], bf[nj >> 1][(nj & 1) * 2 + 1]);
        }
        __syncthreads();
    }

    const int crow = lane >> 2, ccol = (lane & 3) * 2;
#pragma unroll
    for (int mi = 0; mi < 4; mi++) {
#pragma unroll
        for (int nj = 0; nj < 8; nj++) {
            const long mr = m0 + wr * 64 + mi * 16 + crow;
            const int cl = n0 + wc * 64 + nj * 8 + ccol;
            *(float2*)(C + mr * DM + cl)       = make_float2(acc[mi][nj][0], acc[mi][nj][1]);
            *(float2*)(C + (mr + 8) * DM + cl) = make_float2(acc[mi][nj][2], acc[mi][nj][3]);
        }
    }
}

// ---------------------------------------------------------------------------
// Host launcher
// ---------------------------------------------------------------------------
extern "C" void kernel_launch(void* const* d_in, const int* in_sizes, int n_in,
                              void* d_out, int out_size)
{
    const float* x   = (const float*)d_in[0];
    const void*  am  = d_in[1];
    const void*  kpm = d_in[2];
    const float* Wq  = (const float*)d_in[3];
    const float* Wk  = (const float*)d_in[4];
    const float* Wv  = (const float*)d_in[5];
    const float* Wf  = (const float*)d_in[6];
    const float* bfp = (const float*)d_in[7];
    const float* g1  = (const float*)d_in[8];
    const float* b1  = (const float*)d_in[9];
    const float* g2  = (const float*)d_in[10];
    const float* b2  = (const float*)d_in[11];
    float* out = (float*)d_out;

    void *ph, *pz, *pp, *pxh, *pvt, *pzhi, *pzlo, *pwqk, *pwvt, *pwfhi, *pqk;
    void *ptm, *pmf, *pis;
    cudaGetSymbolAddress(&pqk, g_qk);
    cudaGetSymbolAddress(&ph, g_h);
    cudaGetSymbolAddress(&pz, g_z);
    cudaGetSymbolAddress(&pp, g_p);
    cudaGetSymbolAddress(&pxh, g_xh);
    cudaGetSymbolAddress(&pvt, g_vt);
    cudaGetSymbolAddress(&pzhi, g_zhi);
    cudaGetSymbolAddress(&pzlo, g_zlo);
    cudaGetSymbolAddress(&pwqk, g_wqk);
    cudaGetSymbolAddress(&pwvt, g_wvt);
    cudaGetSymbolAddress(&pwfhi, g_wfhi);
    cudaGetSymbolAddress(&ptm, g_tm);
    cudaGetSymbolAddress(&pmf, g_mfin);
    cudaGetSymbolAddress(&pis, g_isum);

    cudaFuncSetAttribute(gemm_mma, cudaFuncAttributeMaxDynamicSharedMemorySize, GM_SMEM);
    cudaFuncSetAttribute(gemm_pv, cudaFuncAttributeMaxDynamicSharedMemorySize, G2_SMEM);
    cudaFuncSetAttribute(attn_probs_kernel, cudaFuncAttributeMaxDynamicSharedMemorySize, AT_SMEM);

    // 0) mask detection + converts
    detect_mask_kernel<<<1, 32>>>(am);
    conv_x_h_kernel<<<(BS_ROWS * DM) / (256 * 4), 256>>>(x);
    concat_wqk_kernel<<<(DM * 32) / 256, 256>>>(Wq, Wk);
    wtrans_kernel<<<dim3(16, 16), dim3(32, 32)>>>(Wv, (__half*)pwvt);
    wtrans_kernel<<<dim3(16, 16), dim3(32, 32)>>>(Wf, (__half*)pwfhi);

    // 1) q|k projection (fp32, protects the sign(rowsum(q)) knife edge)
    gemm_f32<<<dim3(1, BS_ROWS / 64), 256>>>(x, (const float*)pwqk, (float*)pqk,
                                             BS_ROWS, 64, DM);
    rowstats_kernel<<<BS_ROWS / 256, 256>>>(kpm);

    // 2) Vt = (x @ Wv)^T fp16 (tensor cores, transposed store)
    gemm_mma<<<dim3(DM / 128, BS_ROWS / 128, 1), 256, GM_SMEM>>>(
        (const __half*)pxh, nullptr, (const __half*)pwvt, nullptr,
        1, DM, nullptr, (__half*)pvt, nullptr, 1, 0);

    // 3) SINGLE-PASS fused scores + mask + online softmax -> p~ + stats
    attn_probs_kernel<<<dim3(SEQ / 64, BATCH), 256, AT_SMEM>>>(am);

    // 4) h = P @ V (BN=256; normalization folded via fp16 A-fragment scale)
    gemm_pv<<<dim3(DM / 256, SEQ / 128, BATCH), 256, G2_SMEM>>>(
        (const __half*)pp, (const __half*)pvt, (float*)ph,
        (const float*)ptm, (const float*)pmf, (const float*)pis);

    // 5) z = LN(x + h), emit fp16 hi/lo split
    add_ln_kernel<<<BS_ROWS, 128>>>(x, (const float*)ph, g1, b1, (float*)pz,
                                    (__half*)pzhi, (__half*)pzlo);

    // 6) y = leaky(z @ Wf + bf) via 2-pass split-fp16 (zhi + zlo vs Wf_hi)
    gemm_mma<<<dim3(DM / 128, BS_ROWS / 128, 1), 256, GM_SMEM>>>(
        (const __half*)pzhi, (const __half*)pzlo,
        (const __half*)pwfhi, (const __half*)pwfhi,
        2, DM, (float*)ph, nullptr, bfp, 2, DM);

    // 7) out = LN(z + y)
    add_ln_kernel<<<BS_ROWS, 128>>>((const float*)pz, (const float*)ph, g2, b2, out,
                                    nullptr, nullptr);
}